// round 1
// baseline (speedup 1.0000x reference)
#include <cuda_runtime.h>

#define NH 8
#define HD 48
#define CC 384
#define NN 1024
#define BB 16
#define SS 1033   // scores smem row stride (odd -> conflict-free strided row access)

// Scratch (device globals; no allocations allowed)
__device__ float g_q[BB*NH*NN*HD];
__device__ float g_k[BB*NH*NN*HD];
__device__ float g_v[BB*NH*NN*HD];
__device__ float g_o[BB*NN*CC];

// ---------------------------------------------------------------------------
// GEMM 1: qkv[b,n,j] = sum_c x[b,c,n] * w[j,c] + bias[j]
// scattered into g_q/g_k/g_v with layout [b,h,n,d]
// Tiles: BM=128 (n), BN=128 (j), BK=16. 256 threads, 8x8 per thread.
// ---------------------------------------------------------------------------
__global__ __launch_bounds__(256) void gemm_qkv(const float* __restrict__ x,
                                                const float* __restrict__ w,
                                                const float* __restrict__ bias) {
    __shared__ float As[16][128];
    __shared__ float Bs[16][128];
    const int b  = blockIdx.z;
    const int n0 = blockIdx.y * 128;
    const int j0 = blockIdx.x * 128;
    const int t  = threadIdx.x;
    const int tx = t & 15, ty = t >> 4;

    float acc[8][8];
#pragma unroll
    for (int i = 0; i < 8; ++i)
#pragma unroll
        for (int j = 0; j < 8; ++j) acc[i][j] = 0.f;

    const float* xb = x + (size_t)b * CC * NN;

    for (int k0 = 0; k0 < CC; k0 += 16) {
        __syncthreads();
        // A tile: As[k][m] = x[b, k0+k, n0+m]  (m contiguous in gmem)
#pragma unroll
        for (int r = 0; r < 2; ++r) {
            int idx = t + r * 256;
            int kk = idx >> 5, m4 = idx & 31;
            float4 v = *(const float4*)(xb + (size_t)(k0 + kk) * NN + n0 + m4 * 4);
            *(float4*)&As[kk][m4 * 4] = v;
        }
        // B tile: Bs[k][j] = w[(j0+j)*CC + k0+k]  (k contiguous in gmem)
#pragma unroll
        for (int r = 0; r < 2; ++r) {
            int idx = t + r * 256;
            int j = idx >> 2, k4 = idx & 3;
            float4 v = *(const float4*)(w + (size_t)(j0 + j) * CC + k0 + k4 * 4);
            Bs[k4 * 4 + 0][j] = v.x;
            Bs[k4 * 4 + 1][j] = v.y;
            Bs[k4 * 4 + 2][j] = v.z;
            Bs[k4 * 4 + 3][j] = v.w;
        }
        __syncthreads();
#pragma unroll
        for (int kk = 0; kk < 16; ++kk) {
            float a[8], bb[8];
            *(float4*)&a[0]  = *(float4*)&As[kk][ty * 4];
            *(float4*)&a[4]  = *(float4*)&As[kk][64 + ty * 4];
            *(float4*)&bb[0] = *(float4*)&Bs[kk][tx * 4];
            *(float4*)&bb[4] = *(float4*)&Bs[kk][64 + tx * 4];
#pragma unroll
            for (int i = 0; i < 8; ++i)
#pragma unroll
                for (int j = 0; j < 8; ++j) acc[i][j] += a[i] * bb[j];
        }
    }

#pragma unroll
    for (int i = 0; i < 8; ++i) {
        int n = n0 + ((i < 4) ? (ty * 4 + i) : (64 + ty * 4 + i - 4));
#pragma unroll
        for (int j = 0; j < 8; ++j) {
            int jg = j0 + ((j < 4) ? (tx * 4 + j) : (64 + tx * 4 + j - 4));
            float val = acc[i][j] + bias[jg];
            int which = jg / CC;
            int rem = jg - which * CC;
            int h = rem / HD;
            int d = rem - h * HD;
            float* dst = (which == 0) ? g_q : (which == 1) ? g_k : g_v;
            dst[(((size_t)b * NH + h) * NN + n) * HD + d] = val;
        }
    }
}

// ---------------------------------------------------------------------------
// L2-normalize rows of g_q and g_k (row length HD=48). One warp per row.
// ---------------------------------------------------------------------------
__global__ __launch_bounds__(256) void l2norm_kernel() {
    const int NROWS = BB * NH * NN;           // 131072 per tensor
    int warp = (blockIdx.x * 256 + threadIdx.x) >> 5;
    int lane = threadIdx.x & 31;
    float* base = (warp < NROWS) ? g_q : g_k;
    int row = warp & (NROWS - 1);
    float* p = base + (size_t)row * HD;
    float e1 = p[lane];
    float e2 = (lane < 16) ? p[32 + lane] : 0.f;
    float ss = e1 * e1 + e2 * e2;
#pragma unroll
    for (int s = 16; s > 0; s >>= 1) ss += __shfl_xor_sync(0xffffffffu, ss, s);
    float inv = 1.0f / fmaxf(sqrtf(ss), 1e-12f);
    p[lane] = e1 * inv;
    if (lane < 16) p[32 + lane] = e2 * inv;
}

// ---------------------------------------------------------------------------
// Attention: per block = one (b,h) and 32 query rows. Full 1024-key score rows
// in smem; softmax; PV accumulate. Output -> g_o[b][n][c] (c = h*48+d).
// Dynamic smem layout:
//   qs  [48][33]     (q transposed, padded)
//   kv  union: ks_t [48][132]  |  vs [128][48]
//   sc  [32][SS=1033]
//   rsum[32]
// ---------------------------------------------------------------------------
__global__ __launch_bounds__(256) void attn_kernel(const float* __restrict__ temp) {
    extern __shared__ float sm[];
    float* qs   = sm;                    // 48*33   = 1584
    float* kv   = qs + 48 * 33;          // 48*132  = 6336 (>= 128*48 = 6144)
    float* sc   = kv + 48 * 132;         // 32*1033 = 33056
    float* rsum = sc + 32 * SS;          // 32

    const int t  = threadIdx.x;
    const int i0 = blockIdx.x * 32;
    const int bh = blockIdx.y;
    const int h  = bh & (NH - 1);
    const float* qg = g_q + (size_t)bh * NN * HD;
    const float* kg = g_k + (size_t)bh * NN * HD;
    const float* vg = g_v + (size_t)bh * NN * HD;
    const float tmpr = temp[h];

    // load q tile transposed: qs[d][i]
    for (int idx = t; idx < 32 * 12; idx += 256) {
        int i = idx / 12, d4 = idx % 12;
        float4 v = *(const float4*)(qg + (size_t)(i0 + i) * HD + d4 * 4);
        qs[(d4 * 4 + 0) * 33 + i] = v.x;
        qs[(d4 * 4 + 1) * 33 + i] = v.y;
        qs[(d4 * 4 + 2) * 33 + i] = v.z;
        qs[(d4 * 4 + 3) * 33 + i] = v.w;
    }

    // ---- Phase A: scores ----
    const int tyA = t >> 5;   // 0..7  -> i = tyA*4
    const int txA = t & 31;   // 0..31 -> j = txA*4
    for (int t8 = 0; t8 < 8; ++t8) {
        __syncthreads();
        // load K tile transposed: ks_t[d][m], stride 132
        for (int idx = t; idx < 128 * 12; idx += 256) {
            int m = idx / 12, d4 = idx % 12;
            float4 v = *(const float4*)(kg + (size_t)(t8 * 128 + m) * HD + d4 * 4);
            kv[(d4 * 4 + 0) * 132 + m] = v.x;
            kv[(d4 * 4 + 1) * 132 + m] = v.y;
            kv[(d4 * 4 + 2) * 132 + m] = v.z;
            kv[(d4 * 4 + 3) * 132 + m] = v.w;
        }
        __syncthreads();
        float acc[4][4];
#pragma unroll
        for (int u = 0; u < 4; ++u)
#pragma unroll
            for (int w2 = 0; w2 < 4; ++w2) acc[u][w2] = 0.f;
#pragma unroll 4
        for (int d = 0; d < HD; ++d) {
            float4 kf = *(float4*)&kv[d * 132 + txA * 4];
            float q0 = qs[d * 33 + tyA * 4 + 0];
            float q1 = qs[d * 33 + tyA * 4 + 1];
            float q2 = qs[d * 33 + tyA * 4 + 2];
            float q3 = qs[d * 33 + tyA * 4 + 3];
            acc[0][0] += q0 * kf.x; acc[0][1] += q0 * kf.y; acc[0][2] += q0 * kf.z; acc[0][3] += q0 * kf.w;
            acc[1][0] += q1 * kf.x; acc[1][1] += q1 * kf.y; acc[1][2] += q1 * kf.z; acc[1][3] += q1 * kf.w;
            acc[2][0] += q2 * kf.x; acc[2][1] += q2 * kf.y; acc[2][2] += q2 * kf.z; acc[2][3] += q2 * kf.w;
            acc[3][0] += q3 * kf.x; acc[3][1] += q3 * kf.y; acc[3][2] += q3 * kf.z; acc[3][3] += q3 * kf.w;
        }
#pragma unroll
        for (int u = 0; u < 4; ++u)
#pragma unroll
            for (int w2 = 0; w2 < 4; ++w2)
                sc[(tyA * 4 + u) * SS + t8 * 128 + txA * 4 + w2] = acc[u][w2] * tmpr;
    }
    __syncthreads();

    // ---- Phase B: softmax (warp per 4 rows) ----
    {
        int warp = t >> 5, lane = t & 31;
        for (int r = 0; r < 4; ++r) {
            int i = warp * 4 + r;
            float* row = sc + (size_t)i * SS;
            float mx = -1e30f;
            for (int j = lane; j < NN; j += 32) mx = fmaxf(mx, row[j]);
#pragma unroll
            for (int s = 16; s > 0; s >>= 1) mx = fmaxf(mx, __shfl_xor_sync(0xffffffffu, mx, s));
            float sum = 0.f;
            for (int j = lane; j < NN; j += 32) {
                float e = __expf(row[j] - mx);
                row[j] = e;
                sum += e;
            }
#pragma unroll
            for (int s = 16; s > 0; s >>= 1) sum += __shfl_xor_sync(0xffffffffu, sum, s);
            if (lane == 0) rsum[i] = sum;
        }
    }

    // ---- Phase C: out = P @ V ----
    const int ig = t & 15;    // i = 2*ig
    const int dg = t >> 4;    // d = dg*4, active dg<12
    const int ii = ig * 2;
    const int dd = dg * 4;
    float a0x = 0.f, a0y = 0.f, a0z = 0.f, a0w = 0.f;
    float a1x = 0.f, a1y = 0.f, a1z = 0.f, a1w = 0.f;
    for (int t8 = 0; t8 < 8; ++t8) {
        __syncthreads();
        for (int idx = t; idx < 128 * 12; idx += 256) {
            int m = idx / 12, d4 = idx % 12;
            *(float4*)&kv[m * 48 + d4 * 4] =
                *(const float4*)(vg + (size_t)(t8 * 128 + m) * HD + d4 * 4);
        }
        __syncthreads();
        if (dg < 12) {
#pragma unroll 4
            for (int mm = 0; mm < 128; ++mm) {
                int m = t8 * 128 + mm;
                float p0 = sc[ii * SS + m];
                float p1 = sc[(ii + 1) * SS + m];
                float4 v = *(float4*)&kv[mm * 48 + dd];
                a0x += p0 * v.x; a0y += p0 * v.y; a0z += p0 * v.z; a0w += p0 * v.w;
                a1x += p1 * v.x; a1y += p1 * v.y; a1z += p1 * v.z; a1w += p1 * v.w;
            }
        }
    }
    if (dg < 12) {
        float inv0 = 1.0f / rsum[ii];
        float inv1 = 1.0f / rsum[ii + 1];
        int b = bh >> 3;
        float* o0 = g_o + ((size_t)b * NN + i0 + ii) * CC + h * HD + dd;
        float* o1 = o0 + CC;
        float4 r0 = make_float4(a0x * inv0, a0y * inv0, a0z * inv0, a0w * inv0);
        float4 r1 = make_float4(a1x * inv1, a1y * inv1, a1z * inv1, a1w * inv1);
        *(float4*)o0 = r0;
        *(float4*)o1 = r1;
    }
}

// ---------------------------------------------------------------------------
// GEMM 2: out[b,j,n] = sum_c g_o[b,n,c] * proj_w[j,c] + proj_b[j]
// (writes output in [B,C,H,W] layout directly)
// ---------------------------------------------------------------------------
__global__ __launch_bounds__(256) void gemm_proj(const float* __restrict__ w,
                                                 const float* __restrict__ bias,
                                                 float* __restrict__ out) {
    __shared__ float As[16][128];
    __shared__ float Bs[16][128];
    const int b  = blockIdx.z;
    const int n0 = blockIdx.y * 128;
    const int j0 = blockIdx.x * 128;
    const int t  = threadIdx.x;
    const int tx = t & 15, ty = t >> 4;

    float acc[8][8];
#pragma unroll
    for (int i = 0; i < 8; ++i)
#pragma unroll
        for (int j = 0; j < 8; ++j) acc[i][j] = 0.f;

    const float* A = g_o + (size_t)b * NN * CC;

    for (int k0 = 0; k0 < CC; k0 += 16) {
        __syncthreads();
        // A tile transposed-load: As[k][m] = g_o[b, n0+m, k0+k] (k contiguous)
#pragma unroll
        for (int r = 0; r < 2; ++r) {
            int idx = t + r * 256;
            int m = idx >> 2, k4 = idx & 3;
            float4 v = *(const float4*)(A + (size_t)(n0 + m) * CC + k0 + k4 * 4);
            As[k4 * 4 + 0][m] = v.x;
            As[k4 * 4 + 1][m] = v.y;
            As[k4 * 4 + 2][m] = v.z;
            As[k4 * 4 + 3][m] = v.w;
        }
#pragma unroll
        for (int r = 0; r < 2; ++r) {
            int idx = t + r * 256;
            int j = idx >> 2, k4 = idx & 3;
            float4 v = *(const float4*)(w + (size_t)(j0 + j) * CC + k0 + k4 * 4);
            Bs[k4 * 4 + 0][j] = v.x;
            Bs[k4 * 4 + 1][j] = v.y;
            Bs[k4 * 4 + 2][j] = v.z;
            Bs[k4 * 4 + 3][j] = v.w;
        }
        __syncthreads();
#pragma unroll
        for (int kk = 0; kk < 16; ++kk) {
            float a[8], bb[8];
            *(float4*)&a[0]  = *(float4*)&As[kk][ty * 4];
            *(float4*)&a[4]  = *(float4*)&As[kk][64 + ty * 4];
            *(float4*)&bb[0] = *(float4*)&Bs[kk][tx * 4];
            *(float4*)&bb[4] = *(float4*)&Bs[kk][64 + tx * 4];
#pragma unroll
            for (int i = 0; i < 8; ++i)
#pragma unroll
                for (int j = 0; j < 8; ++j) acc[i][j] += a[i] * bb[j];
        }
    }

#pragma unroll
    for (int jj = 0; jj < 8; ++jj) {
        int j = j0 + ((jj < 4) ? (tx * 4 + jj) : (64 + tx * 4 + jj - 4));
        float bj = bias[j];
        float* dst = out + ((size_t)b * CC + j) * NN + n0;
        float4 v0 = make_float4(acc[0][jj] + bj, acc[1][jj] + bj,
                                acc[2][jj] + bj, acc[3][jj] + bj);
        float4 v1 = make_float4(acc[4][jj] + bj, acc[5][jj] + bj,
                                acc[6][jj] + bj, acc[7][jj] + bj);
        *(float4*)(dst + ty * 4) = v0;
        *(float4*)(dst + 64 + ty * 4) = v1;
    }
}

// ---------------------------------------------------------------------------
extern "C" void kernel_launch(void* const* d_in, const int* in_sizes, int n_in,
                              void* d_out, int out_size) {
    const float* x      = (const float*)d_in[0];
    const float* temp   = (const float*)d_in[1];
    const float* qkv_w  = (const float*)d_in[2];
    const float* qkv_b  = (const float*)d_in[3];
    const float* proj_w = (const float*)d_in[4];
    const float* proj_b = (const float*)d_in[5];
    float* out = (float*)d_out;

    static const int ATTN_SMEM = (48 * 33 + 48 * 132 + 32 * SS + 32) * 4;
    cudaFuncSetAttribute(attn_kernel, cudaFuncAttributeMaxDynamicSharedMemorySize,
                         ATTN_SMEM);

    gemm_qkv<<<dim3(9, 8, BB), 256>>>(x, qkv_w, qkv_b);
    l2norm_kernel<<<32768, 256>>>();
    attn_kernel<<<dim3(32, BB * NH), 256, ATTN_SMEM>>>(temp);
    gemm_proj<<<dim3(3, 8, BB), 256>>>(proj_w, proj_b, out);
}

// round 2
// speedup vs baseline: 1.5479x; 1.5479x over previous
#include <cuda_runtime.h>

#define NH 8
#define HD 48
#define CC 384
#define NN 1024
#define BB 16

// Scratch (device globals; no allocations allowed)
__device__ float g_q[BB*NH*NN*HD];
__device__ float g_k[BB*NH*NN*HD];
__device__ float g_v[BB*NH*NN*HD];
__device__ float g_o[BB*NN*CC];

// ---------------------------------------------------------------------------
// GEMM 1: qkv[b,n,j] = sum_c x[b,c,n] * w[j,c] + bias[j]
// scattered into g_q/g_k/g_v with layout [b,h,n,d]
// ---------------------------------------------------------------------------
__global__ __launch_bounds__(256) void gemm_qkv(const float* __restrict__ x,
                                                const float* __restrict__ w,
                                                const float* __restrict__ bias) {
    __shared__ float As[16][128];
    __shared__ float Bs[16][128];
    const int b  = blockIdx.z;
    const int n0 = blockIdx.y * 128;
    const int j0 = blockIdx.x * 128;
    const int t  = threadIdx.x;
    const int tx = t & 15, ty = t >> 4;

    float acc[8][8];
#pragma unroll
    for (int i = 0; i < 8; ++i)
#pragma unroll
        for (int j = 0; j < 8; ++j) acc[i][j] = 0.f;

    const float* xb = x + (size_t)b * CC * NN;

    for (int k0 = 0; k0 < CC; k0 += 16) {
        __syncthreads();
#pragma unroll
        for (int r = 0; r < 2; ++r) {
            int idx = t + r * 256;
            int kk = idx >> 5, m4 = idx & 31;
            float4 v = *(const float4*)(xb + (size_t)(k0 + kk) * NN + n0 + m4 * 4);
            *(float4*)&As[kk][m4 * 4] = v;
        }
#pragma unroll
        for (int r = 0; r < 2; ++r) {
            int idx = t + r * 256;
            int j = idx >> 2, k4 = idx & 3;
            float4 v = *(const float4*)(w + (size_t)(j0 + j) * CC + k0 + k4 * 4);
            Bs[k4 * 4 + 0][j] = v.x;
            Bs[k4 * 4 + 1][j] = v.y;
            Bs[k4 * 4 + 2][j] = v.z;
            Bs[k4 * 4 + 3][j] = v.w;
        }
        __syncthreads();
#pragma unroll
        for (int kk = 0; kk < 16; ++kk) {
            float a[8], bb[8];
            *(float4*)&a[0]  = *(float4*)&As[kk][ty * 4];
            *(float4*)&a[4]  = *(float4*)&As[kk][64 + ty * 4];
            *(float4*)&bb[0] = *(float4*)&Bs[kk][tx * 4];
            *(float4*)&bb[4] = *(float4*)&Bs[kk][64 + tx * 4];
#pragma unroll
            for (int i = 0; i < 8; ++i)
#pragma unroll
                for (int j = 0; j < 8; ++j) acc[i][j] += a[i] * bb[j];
        }
    }

#pragma unroll
    for (int i = 0; i < 8; ++i) {
        int n = n0 + ((i < 4) ? (ty * 4 + i) : (64 + ty * 4 + i - 4));
#pragma unroll
        for (int j = 0; j < 8; ++j) {
            int jg = j0 + ((j < 4) ? (tx * 4 + j) : (64 + tx * 4 + j - 4));
            float val = acc[i][j] + bias[jg];
            int which = jg / CC;
            int rem = jg - which * CC;
            int h = rem / HD;
            int d = rem - h * HD;
            float* dst = (which == 0) ? g_q : (which == 1) ? g_k : g_v;
            dst[(((size_t)b * NH + h) * NN + n) * HD + d] = val;
        }
    }
}

// ---------------------------------------------------------------------------
// L2-normalize rows of g_q and g_k (row length HD=48). One warp per row.
// ---------------------------------------------------------------------------
__global__ __launch_bounds__(256) void l2norm_kernel() {
    const int NROWS = BB * NH * NN;
    int warp = (blockIdx.x * 256 + threadIdx.x) >> 5;
    int lane = threadIdx.x & 31;
    float* base = (warp < NROWS) ? g_q : g_k;
    int row = warp & (NROWS - 1);
    float* p = base + (size_t)row * HD;
    float e1 = p[lane];
    float e2 = (lane < 16) ? p[32 + lane] : 0.f;
    float ss = e1 * e1 + e2 * e2;
#pragma unroll
    for (int s = 16; s > 0; s >>= 1) ss += __shfl_xor_sync(0xffffffffu, ss, s);
    float inv = 1.0f / fmaxf(sqrtf(ss), 1e-12f);
    p[lane] = e1 * inv;
    if (lane < 16) p[32 + lane] = e2 * inv;
}

// ---------------------------------------------------------------------------
// Flash attention: block = (b,h) x 64 query rows. Online softmax over 16
// key tiles of 64. S in regs (4x4/thread), O in regs (12/thread), P staged
// through smem once per tile. Smem = 57.6 KB -> 2 CTAs/SM.
//
// Smem layout (floats):
//   qT [48][68]  q transposed            3264
//   kT [48][68]  k tile transposed       3264
//   vs [64][52]  v tile row-major        3328
//   P  [64][68]  exp(S - m) staging      4352
//   mrow[64], srow[64], csm[64]           192
// ---------------------------------------------------------------------------
#define QT_OFF 0
#define KT_OFF 3264
#define VS_OFF 6528
#define P_OFF  9856
#define M_OFF  14208
#define S_OFF  14272
#define C_OFF  14336
#define ATTN_SMEM_FLOATS 14400

__global__ __launch_bounds__(256) void attn_flash(const float* __restrict__ temp) {
    extern __shared__ float sm[];
    float* qT   = sm + QT_OFF;
    float* kT   = sm + KT_OFF;
    float* vs   = sm + VS_OFF;
    float* Ps   = sm + P_OFF;
    float* mrow = sm + M_OFF;
    float* srow = sm + S_OFF;
    float* csm  = sm + C_OFF;

    const int t  = threadIdx.x;
    const int i0 = blockIdx.x * 64;
    const int bh = blockIdx.y;
    const int h  = bh & (NH - 1);
    const float* qg = g_q + (size_t)bh * NN * HD;
    const float* kg = g_k + (size_t)bh * NN * HD;
    const float* vg = g_v + (size_t)bh * NN * HD;
    const float tmpr = temp[h];

    // S-phase thread mapping: 16x16 grid, 4 rows x 4 cols each
    const int tx = t & 15;        // key cols tx*4 .. tx*4+3
    const int ty = t >> 4;        // q rows  ty*4 .. ty*4+3

    // PV-phase mapping: warp -> 8 q rows, lane>>2 selects row, lane&3 -> d group
    const int warp = t >> 5;
    const int lane = t & 31;
    const int qv = warp * 8 + (lane >> 2);
    const int d0 = (lane & 3) * 12;

    // load q tile transposed
    for (int idx = t; idx < 64 * 12; idx += 256) {
        int i = idx / 12, d4 = idx % 12;
        float4 v = *(const float4*)(qg + (size_t)(i0 + i) * HD + d4 * 4);
        qT[(d4 * 4 + 0) * 68 + i] = v.x;
        qT[(d4 * 4 + 1) * 68 + i] = v.y;
        qT[(d4 * 4 + 2) * 68 + i] = v.z;
        qT[(d4 * 4 + 3) * 68 + i] = v.w;
    }
    if (t < 64) { mrow[t] = -1e30f; srow[t] = 0.f; }

    float o[12];
#pragma unroll
    for (int i = 0; i < 12; ++i) o[i] = 0.f;

    for (int t16 = 0; t16 < 16; ++t16) {
        const int k0 = t16 * 64;
        __syncthreads();   // prior PV done -> safe to overwrite kT/vs
        // load K tile transposed + V tile
        for (int idx = t; idx < 64 * 12; idx += 256) {
            int m = idx / 12, d4 = idx % 12;
            float4 kv4 = *(const float4*)(kg + (size_t)(k0 + m) * HD + d4 * 4);
            kT[(d4 * 4 + 0) * 68 + m] = kv4.x;
            kT[(d4 * 4 + 1) * 68 + m] = kv4.y;
            kT[(d4 * 4 + 2) * 68 + m] = kv4.z;
            kT[(d4 * 4 + 3) * 68 + m] = kv4.w;
            float4 vv4 = *(const float4*)(vg + (size_t)(k0 + m) * HD + d4 * 4);
            *(float4*)&vs[m * 52 + d4 * 4] = vv4;
        }
        __syncthreads();

        // ---- S = q . k^T (4x4 per thread) ----
        float acc[4][4];
#pragma unroll
        for (int u = 0; u < 4; ++u)
#pragma unroll
            for (int w2 = 0; w2 < 4; ++w2) acc[u][w2] = 0.f;
#pragma unroll 6
        for (int d = 0; d < HD; ++d) {
            float4 kf = *(float4*)&kT[d * 68 + tx * 4];
            float4 qf = *(float4*)&qT[d * 68 + ty * 4];
            acc[0][0] += qf.x * kf.x; acc[0][1] += qf.x * kf.y; acc[0][2] += qf.x * kf.z; acc[0][3] += qf.x * kf.w;
            acc[1][0] += qf.y * kf.x; acc[1][1] += qf.y * kf.y; acc[1][2] += qf.y * kf.z; acc[1][3] += qf.y * kf.w;
            acc[2][0] += qf.z * kf.x; acc[2][1] += qf.z * kf.y; acc[2][2] += qf.z * kf.z; acc[2][3] += qf.z * kf.w;
            acc[3][0] += qf.w * kf.x; acc[3][1] += qf.w * kf.y; acc[3][2] += qf.w * kf.z; acc[3][3] += qf.w * kf.w;
        }

        // ---- online softmax (row groups = 16 lanes sharing ty) ----
#pragma unroll
        for (int u = 0; u < 4; ++u) {
            int row = ty * 4 + u;
            float s0 = acc[u][0] * tmpr, s1 = acc[u][1] * tmpr;
            float s2 = acc[u][2] * tmpr, s3 = acc[u][3] * tmpr;
            float rm = fmaxf(fmaxf(s0, s1), fmaxf(s2, s3));
#pragma unroll
            for (int s = 8; s > 0; s >>= 1) rm = fmaxf(rm, __shfl_xor_sync(0xffffffffu, rm, s));
            float mold = mrow[row];
            float mnew = fmaxf(mold, rm);
            float p0 = __expf(s0 - mnew), p1 = __expf(s1 - mnew);
            float p2 = __expf(s2 - mnew), p3 = __expf(s3 - mnew);
            float rs = p0 + p1 + p2 + p3;
#pragma unroll
            for (int s = 8; s > 0; s >>= 1) rs += __shfl_xor_sync(0xffffffffu, rs, s);
            if (tx == 0) {
                float c = __expf(mold - mnew);
                srow[row] = srow[row] * c + rs;
                mrow[row] = mnew;
                csm[row]  = c;
            }
            *(float4*)&Ps[row * 68 + tx * 4] = make_float4(p0, p1, p2, p3);
        }
        __syncthreads();

        // ---- PV: O = c*O + P @ V ----
        {
            float c = csm[qv];
#pragma unroll
            for (int i = 0; i < 12; ++i) o[i] *= c;
            const float* prow = Ps + qv * 68;
#pragma unroll 4
            for (int m4 = 0; m4 < 16; ++m4) {
                float4 p4 = *(const float4*)(prow + m4 * 4);
#pragma unroll
                for (int e = 0; e < 4; ++e) {
                    int m = m4 * 4 + e;
                    float pm = (e == 0) ? p4.x : (e == 1) ? p4.y : (e == 2) ? p4.z : p4.w;
                    float4 v0 = *(float4*)&vs[m * 52 + d0];
                    float4 v1 = *(float4*)&vs[m * 52 + d0 + 4];
                    float4 v2 = *(float4*)&vs[m * 52 + d0 + 8];
                    o[0] += pm * v0.x; o[1]  += pm * v0.y; o[2]  += pm * v0.z; o[3]  += pm * v0.w;
                    o[4] += pm * v1.x; o[5]  += pm * v1.y; o[6]  += pm * v1.z; o[7]  += pm * v1.w;
                    o[8] += pm * v2.x; o[9]  += pm * v2.y; o[10] += pm * v2.z; o[11] += pm * v2.w;
                }
            }
        }
    }

    // write out (normalized)
    {
        float inv = 1.0f / srow[qv];
        int b = bh >> 3;
        float* op = g_o + ((size_t)b * NN + i0 + qv) * CC + h * HD + d0;
        *(float4*)(op + 0) = make_float4(o[0] * inv, o[1] * inv, o[2]  * inv, o[3]  * inv);
        *(float4*)(op + 4) = make_float4(o[4] * inv, o[5] * inv, o[6]  * inv, o[7]  * inv);
        *(float4*)(op + 8) = make_float4(o[8] * inv, o[9] * inv, o[10] * inv, o[11] * inv);
    }
}

// ---------------------------------------------------------------------------
// GEMM 2: out[b,j,n] = sum_c g_o[b,n,c] * proj_w[j,c] + proj_b[j]
// ---------------------------------------------------------------------------
__global__ __launch_bounds__(256) void gemm_proj(const float* __restrict__ w,
                                                 const float* __restrict__ bias,
                                                 float* __restrict__ out) {
    __shared__ float As[16][128];
    __shared__ float Bs[16][128];
    const int b  = blockIdx.z;
    const int n0 = blockIdx.y * 128;
    const int j0 = blockIdx.x * 128;
    const int t  = threadIdx.x;
    const int tx = t & 15, ty = t >> 4;

    float acc[8][8];
#pragma unroll
    for (int i = 0; i < 8; ++i)
#pragma unroll
        for (int j = 0; j < 8; ++j) acc[i][j] = 0.f;

    const float* A = g_o + (size_t)b * NN * CC;

    for (int k0 = 0; k0 < CC; k0 += 16) {
        __syncthreads();
#pragma unroll
        for (int r = 0; r < 2; ++r) {
            int idx = t + r * 256;
            int m = idx >> 2, k4 = idx & 3;
            float4 v = *(const float4*)(A + (size_t)(n0 + m) * CC + k0 + k4 * 4);
            As[k4 * 4 + 0][m] = v.x;
            As[k4 * 4 + 1][m] = v.y;
            As[k4 * 4 + 2][m] = v.z;
            As[k4 * 4 + 3][m] = v.w;
        }
#pragma unroll
        for (int r = 0; r < 2; ++r) {
            int idx = t + r * 256;
            int j = idx >> 2, k4 = idx & 3;
            float4 v = *(const float4*)(w + (size_t)(j0 + j) * CC + k0 + k4 * 4);
            Bs[k4 * 4 + 0][j] = v.x;
            Bs[k4 * 4 + 1][j] = v.y;
            Bs[k4 * 4 + 2][j] = v.z;
            Bs[k4 * 4 + 3][j] = v.w;
        }
        __syncthreads();
#pragma unroll
        for (int kk = 0; kk < 16; ++kk) {
            float a[8], bb[8];
            *(float4*)&a[0]  = *(float4*)&As[kk][ty * 4];
            *(float4*)&a[4]  = *(float4*)&As[kk][64 + ty * 4];
            *(float4*)&bb[0] = *(float4*)&Bs[kk][tx * 4];
            *(float4*)&bb[4] = *(float4*)&Bs[kk][64 + tx * 4];
#pragma unroll
            for (int i = 0; i < 8; ++i)
#pragma unroll
                for (int j = 0; j < 8; ++j) acc[i][j] += a[i] * bb[j];
        }
    }

#pragma unroll
    for (int jj = 0; jj < 8; ++jj) {
        int j = j0 + ((jj < 4) ? (tx * 4 + jj) : (64 + tx * 4 + jj - 4));
        float bj = bias[j];
        float* dst = out + ((size_t)b * CC + j) * NN + n0;
        float4 v0 = make_float4(acc[0][jj] + bj, acc[1][jj] + bj,
                                acc[2][jj] + bj, acc[3][jj] + bj);
        float4 v1 = make_float4(acc[4][jj] + bj, acc[5][jj] + bj,
                                acc[6][jj] + bj, acc[7][jj] + bj);
        *(float4*)(dst + ty * 4) = v0;
        *(float4*)(dst + 64 + ty * 4) = v1;
    }
}

// ---------------------------------------------------------------------------
extern "C" void kernel_launch(void* const* d_in, const int* in_sizes, int n_in,
                              void* d_out, int out_size) {
    const float* x      = (const float*)d_in[0];
    const float* temp   = (const float*)d_in[1];
    const float* qkv_w  = (const float*)d_in[2];
    const float* qkv_b  = (const float*)d_in[3];
    const float* proj_w = (const float*)d_in[4];
    const float* proj_b = (const float*)d_in[5];
    float* out = (float*)d_out;

    static const int ATTN_SMEM = ATTN_SMEM_FLOATS * 4;
    cudaFuncSetAttribute(attn_flash, cudaFuncAttributeMaxDynamicSharedMemorySize,
                         ATTN_SMEM);

    gemm_qkv<<<dim3(9, 8, BB), 256>>>(x, qkv_w, qkv_b);
    l2norm_kernel<<<32768, 256>>>();
    attn_flash<<<dim3(16, BB * NH), 256, ATTN_SMEM>>>(temp);
    gemm_proj<<<dim3(3, 8, BB), 256>>>(proj_b ? proj_w : proj_w, proj_b, out);
}

// round 7
// speedup vs baseline: 3.2307x; 2.0872x over previous
#include <cuda_runtime.h>
#include <cstdint>

#define NH 8
#define HD 48
#define CC 384
#define NN 1024
#define BB 16

// Scratch (device globals; no allocations allowed)
__device__ float g_q[BB*NH*NN*HD];
__device__ float g_k[BB*NH*NN*HD];
__device__ float g_v[BB*NH*NN*HD];
__device__ float g_o[BB*NN*CC];

// ---------------------------------------------------------------------------
// tf32 helpers (sm_80+ ISA only; no sm_103a-specific instructions)
// ---------------------------------------------------------------------------
__device__ __forceinline__ float tf32r(float x) {
    uint32_t r;
    asm("cvt.rna.tf32.f32 %0, %1;" : "=r"(r) : "f"(x));
    return __uint_as_float(r);
}
__device__ __forceinline__ void mma_tf32(float* acc, const float* a, float b0, float b1) {
    asm volatile(
        "mma.sync.aligned.m16n8k8.row.col.f32.tf32.tf32.f32 "
        "{%0,%1,%2,%3}, {%4,%5,%6,%7}, {%8,%9}, {%0,%1,%2,%3};"
        : "+f"(acc[0]), "+f"(acc[1]), "+f"(acc[2]), "+f"(acc[3])
        : "r"(__float_as_uint(a[0])), "r"(__float_as_uint(a[1])),
          "r"(__float_as_uint(a[2])), "r"(__float_as_uint(a[3])),
          "r"(__float_as_uint(b0)),  "r"(__float_as_uint(b1)));
}

// ---------------------------------------------------------------------------
// GEMM 1: qkv[b,n,j] = sum_c x[b,c,n] * w[j,c] + bias[j]  (fp32 SIMT)
// ---------------------------------------------------------------------------
__global__ __launch_bounds__(256) void gemm_qkv(const float* __restrict__ x,
                                                const float* __restrict__ w,
                                                const float* __restrict__ bias) {
    __shared__ float As[16][128];
    __shared__ float Bs[16][128];
    const int b  = blockIdx.z;
    const int n0 = blockIdx.y * 128;
    const int j0 = blockIdx.x * 128;
    const int t  = threadIdx.x;
    const int tx = t & 15, ty = t >> 4;

    float acc[8][8];
#pragma unroll
    for (int i = 0; i < 8; ++i)
#pragma unroll
        for (int j = 0; j < 8; ++j) acc[i][j] = 0.f;

    const float* xb = x + (size_t)b * CC * NN;

    for (int k0 = 0; k0 < CC; k0 += 16) {
        __syncthreads();
#pragma unroll
        for (int r = 0; r < 2; ++r) {
            int idx = t + r * 256;
            int kk = idx >> 5, m4 = idx & 31;
            float4 v = *(const float4*)(xb + (size_t)(k0 + kk) * NN + n0 + m4 * 4);
            *(float4*)&As[kk][m4 * 4] = v;
        }
#pragma unroll
        for (int r = 0; r < 2; ++r) {
            int idx = t + r * 256;
            int j = idx >> 2, k4 = idx & 3;
            float4 v = *(const float4*)(w + (size_t)(j0 + j) * CC + k0 + k4 * 4);
            Bs[k4 * 4 + 0][j] = v.x;
            Bs[k4 * 4 + 1][j] = v.y;
            Bs[k4 * 4 + 2][j] = v.z;
            Bs[k4 * 4 + 3][j] = v.w;
        }
        __syncthreads();
#pragma unroll
        for (int kk = 0; kk < 16; ++kk) {
            float a[8], bb[8];
            *(float4*)&a[0]  = *(float4*)&As[kk][ty * 4];
            *(float4*)&a[4]  = *(float4*)&As[kk][64 + ty * 4];
            *(float4*)&bb[0] = *(float4*)&Bs[kk][tx * 4];
            *(float4*)&bb[4] = *(float4*)&Bs[kk][64 + tx * 4];
#pragma unroll
            for (int i = 0; i < 8; ++i)
#pragma unroll
                for (int j = 0; j < 8; ++j) acc[i][j] += a[i] * bb[j];
        }
    }

#pragma unroll
    for (int i = 0; i < 8; ++i) {
        int n = n0 + ((i < 4) ? (ty * 4 + i) : (64 + ty * 4 + i - 4));
#pragma unroll
        for (int j = 0; j < 8; ++j) {
            int jg = j0 + ((j < 4) ? (tx * 4 + j) : (64 + tx * 4 + j - 4));
            float val = acc[i][j] + bias[jg];
            int which = jg / CC;
            int rem = jg - which * CC;
            int h = rem / HD;
            int d = rem - h * HD;
            float* dst = (which == 0) ? g_q : (which == 1) ? g_k : g_v;
            dst[(((size_t)b * NH + h) * NN + n) * HD + d] = val;
        }
    }
}

// ---------------------------------------------------------------------------
// L2-normalize rows of g_q and g_k. One warp per row.
// ---------------------------------------------------------------------------
__global__ __launch_bounds__(256) void l2norm_kernel() {
    const int NROWS = BB * NH * NN;
    int warp = (blockIdx.x * 256 + threadIdx.x) >> 5;
    int lane = threadIdx.x & 31;
    float* base = (warp < NROWS) ? g_q : g_k;
    int row = warp & (NROWS - 1);
    float* p = base + (size_t)row * HD;
    float e1 = p[lane];
    float e2 = (lane < 16) ? p[32 + lane] : 0.f;
    float ss = e1 * e1 + e2 * e2;
#pragma unroll
    for (int s = 16; s > 0; s >>= 1) ss += __shfl_xor_sync(0xffffffffu, ss, s);
    float inv = 1.0f / fmaxf(sqrtf(ss), 1e-12f);
    p[lane] = e1 * inv;
    if (lane < 16) p[32 + lane] = e2 * inv;
}

// ---------------------------------------------------------------------------
// Tensor-core flash attention via mma.sync tf32 (m16n8k8).
// CTA = (b,h) x 128 q rows; 8 warps x M=16. 16 key tiles of 64.
// Fixed-bound softmax: q,k unit vectors => |q.k|<=1 => max bound = |t|.
//   S_w[16x64] = Q_w . K^T      (fragments; Q regs persist across tiles)
//   P = exp(t*S - |t|)          (stored to per-warp smem, regathered as A)
//   O_w[16x48] += P . V         (fp32 accumulators, no rescale ever)
// Smem (floats): Ks[64][52] | Vs[64][72] | Ps[8][16][68]  = 66560 B
// Q staged once through the Ks/Vs region (stride 52) before the main loop.
// ---------------------------------------------------------------------------
#define KS_STRIDE 52
#define VS_STRIDE 72
#define PS_STRIDE 68
#define SM_VS_F   (64 * KS_STRIDE)                 // 3328
#define SM_PS_F   (SM_VS_F + 64 * VS_STRIDE)       // 7936
#define ATTN_SMEM_F (SM_PS_F + 8 * 16 * PS_STRIDE) // 16640 floats = 66560 B

__global__ __launch_bounds__(256) void attn_mma(const float* __restrict__ temp) {
    extern __shared__ float sm[];
    float* Ks = sm;
    float* Vs = sm + SM_VS_F;
    float* Ps = sm + SM_PS_F;

    const int t = threadIdx.x;
    const int w = t >> 5;
    const int lane = t & 31;
    const int lr = lane >> 2;   // 0..7
    const int lc = lane & 3;    // 0..3
    const int i0 = blockIdx.x * 128;
    const int bh = blockIdx.y;
    const int h  = bh & (NH - 1);
    const float* qg = g_q + (size_t)bh * NN * HD;
    const float* kg = g_k + (size_t)bh * NN * HD;
    const float* vg = g_v + (size_t)bh * NN * HD;
    const float tpr = temp[h];
    const float mterm = fabsf(tpr);

    // ---- stage Q tile [128][48] into smem (stride 52), tf32-rounded ----
    for (int idx = t; idx < 128 * 12; idx += 256) {
        int r = idx / 12, c4 = idx % 12;
        float4 v = *(const float4*)(qg + (size_t)(i0 + r) * HD + c4 * 4);
        v.x = tf32r(v.x); v.y = tf32r(v.y); v.z = tf32r(v.z); v.w = tf32r(v.w);
        *(float4*)&sm[r * KS_STRIDE + c4 * 4] = v;
    }
    __syncthreads();

    // ---- load persistent Q fragments (A of m16n8k8): 6 k-blocks x 4 regs ----
    float qf[6][4];
    {
        const int mr = w * 16 + lr;
#pragma unroll
        for (int kb = 0; kb < 6; ++kb) {
            qf[kb][0] = sm[mr * KS_STRIDE + kb * 8 + lc];
            qf[kb][1] = sm[(mr + 8) * KS_STRIDE + kb * 8 + lc];
            qf[kb][2] = sm[mr * KS_STRIDE + kb * 8 + lc + 4];
            qf[kb][3] = sm[(mr + 8) * KS_STRIDE + kb * 8 + lc + 4];
        }
    }

    float oacc[6][4];
#pragma unroll
    for (int i = 0; i < 6; ++i)
#pragma unroll
        for (int j = 0; j < 4; ++j) oacc[i][j] = 0.f;
    float rsum0 = 0.f, rsum1 = 0.f;
    float* Pw = Ps + w * 16 * PS_STRIDE;

    for (int kt = 0; kt < 16; ++kt) {
        const int k0 = kt * 64;
        __syncthreads();   // previous tile fully consumed (also: Q stage done)
        // ---- load K[64][48] (stride 52) and V[64][48] (stride 72), tf32 ----
        for (int idx = t; idx < 64 * 12; idx += 256) {
            int n = idx / 12, c4 = idx % 12;
            float4 v = *(const float4*)(kg + (size_t)(k0 + n) * HD + c4 * 4);
            v.x = tf32r(v.x); v.y = tf32r(v.y); v.z = tf32r(v.z); v.w = tf32r(v.w);
            *(float4*)&Ks[n * KS_STRIDE + c4 * 4] = v;
            float4 u = *(const float4*)(vg + (size_t)(k0 + n) * HD + c4 * 4);
            u.x = tf32r(u.x); u.y = tf32r(u.y); u.z = tf32r(u.z); u.w = tf32r(u.w);
            *(float4*)&Vs[n * VS_STRIDE + c4 * 4] = u;
        }
        __syncthreads();

        // ---- S = Q . K^T : 8 n-blocks x 6 k-blocks ----
        float sacc[8][4];
#pragma unroll
        for (int i = 0; i < 8; ++i)
#pragma unroll
            for (int j = 0; j < 4; ++j) sacc[i][j] = 0.f;
#pragma unroll
        for (int nb = 0; nb < 8; ++nb) {
            const float* kbase = Ks + (nb * 8 + lr) * KS_STRIDE + lc;
#pragma unroll
            for (int kb = 0; kb < 6; ++kb) {
                float b0 = kbase[kb * 8];
                float b1 = kbase[kb * 8 + 4];
                mma_tf32(sacc[nb], qf[kb], b0, b1);
            }
        }

        // ---- softmax (fixed bound) + stage P to per-warp smem ----
#pragma unroll
        for (int nb = 0; nb < 8; ++nb) {
            float p0 = __expf(fmaf(sacc[nb][0], tpr, -mterm));
            float p1 = __expf(fmaf(sacc[nb][1], tpr, -mterm));
            float p2 = __expf(fmaf(sacc[nb][2], tpr, -mterm));
            float p3 = __expf(fmaf(sacc[nb][3], tpr, -mterm));
            rsum0 += p0 + p1;
            rsum1 += p2 + p3;
            *(float2*)&Pw[lr * PS_STRIDE + nb * 8 + 2 * lc] =
                make_float2(tf32r(p0), tf32r(p1));
            *(float2*)&Pw[(lr + 8) * PS_STRIDE + nb * 8 + 2 * lc] =
                make_float2(tf32r(p2), tf32r(p3));
        }
        __syncwarp();

        // ---- O += P . V : A from Pw, B from Vs ----
#pragma unroll
        for (int kb2 = 0; kb2 < 8; ++kb2) {
            float af[4];
            af[0] = Pw[lr * PS_STRIDE + kb2 * 8 + lc];
            af[1] = Pw[(lr + 8) * PS_STRIDE + kb2 * 8 + lc];
            af[2] = Pw[lr * PS_STRIDE + kb2 * 8 + lc + 4];
            af[3] = Pw[(lr + 8) * PS_STRIDE + kb2 * 8 + lc + 4];
            const float* vb0 = Vs + (kb2 * 8 + lc) * VS_STRIDE + lr;
            const float* vb1 = Vs + (kb2 * 8 + lc + 4) * VS_STRIDE + lr;
#pragma unroll
            for (int nb2 = 0; nb2 < 6; ++nb2) {
                mma_tf32(oacc[nb2], af, vb0[nb2 * 8], vb1[nb2 * 8]);
            }
        }
    }

    // ---- reduce row sums within 4-lane groups, write normalized O ----
    rsum0 += __shfl_xor_sync(0xffffffffu, rsum0, 1);
    rsum0 += __shfl_xor_sync(0xffffffffu, rsum0, 2);
    rsum1 += __shfl_xor_sync(0xffffffffu, rsum1, 1);
    rsum1 += __shfl_xor_sync(0xffffffffu, rsum1, 2);
    const float inv0 = 1.0f / rsum0;
    const float inv1 = 1.0f / rsum1;
    const int b = bh >> 3;
    const int row0 = i0 + w * 16 + lr;
    float* o0 = g_o + ((size_t)b * NN + row0) * CC + h * HD;
    float* o1 = o0 + 8 * CC;
#pragma unroll
    for (int nb = 0; nb < 6; ++nb) {
        *(float2*)&o0[nb * 8 + 2 * lc] = make_float2(oacc[nb][0] * inv0, oacc[nb][1] * inv0);
        *(float2*)&o1[nb * 8 + 2 * lc] = make_float2(oacc[nb][2] * inv1, oacc[nb][3] * inv1);
    }
}

// ---------------------------------------------------------------------------
// GEMM 2: out[b,j,n] = sum_c g_o[b,n,c] * proj_w[j,c] + proj_b[j]
// ---------------------------------------------------------------------------
__global__ __launch_bounds__(256) void gemm_proj(const float* __restrict__ w,
                                                 const float* __restrict__ bias,
                                                 float* __restrict__ out) {
    __shared__ float As[16][128];
    __shared__ float Bs[16][128];
    const int b  = blockIdx.z;
    const int n0 = blockIdx.y * 128;
    const int j0 = blockIdx.x * 128;
    const int t  = threadIdx.x;
    const int tx = t & 15, ty = t >> 4;

    float acc[8][8];
#pragma unroll
    for (int i = 0; i < 8; ++i)
#pragma unroll
        for (int j = 0; j < 8; ++j) acc[i][j] = 0.f;

    const float* A = g_o + (size_t)b * NN * CC;

    for (int k0 = 0; k0 < CC; k0 += 16) {
        __syncthreads();
#pragma unroll
        for (int r = 0; r < 2; ++r) {
            int idx = t + r * 256;
            int m = idx >> 2, k4 = idx & 3;
            float4 v = *(const float4*)(A + (size_t)(n0 + m) * CC + k0 + k4 * 4);
            As[k4 * 4 + 0][m] = v.x;
            As[k4 * 4 + 1][m] = v.y;
            As[k4 * 4 + 2][m] = v.z;
            As[k4 * 4 + 3][m] = v.w;
        }
#pragma unroll
        for (int r = 0; r < 2; ++r) {
            int idx = t + r * 256;
            int j = idx >> 2, k4 = idx & 3;
            float4 v = *(const float4*)(w + (size_t)(j0 + j) * CC + k0 + k4 * 4);
            Bs[k4 * 4 + 0][j] = v.x;
            Bs[k4 * 4 + 1][j] = v.y;
            Bs[k4 * 4 + 2][j] = v.z;
            Bs[k4 * 4 + 3][j] = v.w;
        }
        __syncthreads();
#pragma unroll
        for (int kk = 0; kk < 16; ++kk) {
            float a[8], bb[8];
            *(float4*)&a[0]  = *(float4*)&As[kk][ty * 4];
            *(float4*)&a[4]  = *(float4*)&As[kk][64 + ty * 4];
            *(float4*)&bb[0] = *(float4*)&Bs[kk][tx * 4];
            *(float4*)&bb[4] = *(float4*)&Bs[kk][64 + tx * 4];
#pragma unroll
            for (int i = 0; i < 8; ++i)
#pragma unroll
                for (int j = 0; j < 8; ++j) acc[i][j] += a[i] * bb[j];
        }
    }

#pragma unroll
    for (int jj = 0; jj < 8; ++jj) {
        int j = j0 + ((jj < 4) ? (tx * 4 + jj) : (64 + tx * 4 + jj - 4));
        float bj = bias[j];
        float* dst = out + ((size_t)b * CC + j) * NN + n0;
        float4 v0 = make_float4(acc[0][jj] + bj, acc[1][jj] + bj,
                                acc[2][jj] + bj, acc[3][jj] + bj);
        float4 v1 = make_float4(acc[4][jj] + bj, acc[5][jj] + bj,
                                acc[6][jj] + bj, acc[7][jj] + bj);
        *(float4*)(dst + ty * 4) = v0;
        *(float4*)(dst + 64 + ty * 4) = v1;
    }
}

// ---------------------------------------------------------------------------
extern "C" void kernel_launch(void* const* d_in, const int* in_sizes, int n_in,
                              void* d_out, int out_size) {
    const float* x      = (const float*)d_in[0];
    const float* temp   = (const float*)d_in[1];
    const float* qkv_w  = (const float*)d_in[2];
    const float* qkv_b  = (const float*)d_in[3];
    const float* proj_w = (const float*)d_in[4];
    const float* proj_b = (const float*)d_in[5];
    float* out = (float*)d_out;

    static const int ATTN_SMEM = ATTN_SMEM_F * 4;   // 66560 bytes
    cudaFuncSetAttribute(attn_mma, cudaFuncAttributeMaxDynamicSharedMemorySize,
                         ATTN_SMEM);

    gemm_qkv<<<dim3(9, 8, BB), 256>>>(x, qkv_w, qkv_b);
    l2norm_kernel<<<32768, 256>>>();
    attn_mma<<<dim3(8, BB * NH), 256, ATTN_SMEM>>>(temp);
    gemm_proj<<<dim3(3, 8, BB), 256>>>(proj_w, proj_b, out);
}

// round 8
// speedup vs baseline: 4.2405x; 1.3126x over previous
#include <cuda_runtime.h>
#include <cstdint>

#define NH 8
#define HD 48
#define CC 384
#define NN 1024
#define BB 16

// Scratch (device globals; no allocations allowed)
__device__ float g_q[BB*NH*NN*HD];
__device__ float g_k[BB*NH*NN*HD];
__device__ float g_v[BB*NH*NN*HD];
__device__ float g_o[BB*NN*CC];

// ---------------------------------------------------------------------------
// tf32 helpers (sm_80+ baseline ISA)
// ---------------------------------------------------------------------------
__device__ __forceinline__ float tf32r(float x) {
    uint32_t r;
    asm("cvt.rna.tf32.f32 %0, %1;" : "=r"(r) : "f"(x));
    return __uint_as_float(r);
}
__device__ __forceinline__ void mma_tf32(float* acc, const float* a, float b0, float b1) {
    asm volatile(
        "mma.sync.aligned.m16n8k8.row.col.f32.tf32.tf32.f32 "
        "{%0,%1,%2,%3}, {%4,%5,%6,%7}, {%8,%9}, {%0,%1,%2,%3};"
        : "+f"(acc[0]), "+f"(acc[1]), "+f"(acc[2]), "+f"(acc[3])
        : "r"(__float_as_uint(a[0])), "r"(__float_as_uint(a[1])),
          "r"(__float_as_uint(a[2])), "r"(__float_as_uint(a[3])),
          "r"(__float_as_uint(b0)),  "r"(__float_as_uint(b1)));
}

// ===========================================================================
// GEMM 1 (tensor core tf32): qkv[b,n,j] = sum_c x[b,c,n]*w[j,c] + bias[j]
// CTA tile 128(m=n) x 64(j), K-step 32. 8 warps as 4(m) x 2(n), warp 32x32.
// A smem [m][k] stride 36 (bank-free frags), B smem [j][k] stride 36.
// Scatter epilogue into g_q/g_k/g_v (64-col block stays in one tensor).
// ===========================================================================
__global__ __launch_bounds__(256) void gemm_qkv_tc(const float* __restrict__ x,
                                                   const float* __restrict__ w,
                                                   const float* __restrict__ bias) {
    __shared__ float As[128 * 36];
    __shared__ float Bs[64 * 36];
    const int b  = blockIdx.z;
    const int m0 = blockIdx.y * 128;
    const int j0 = blockIdx.x * 64;
    const int t  = threadIdx.x;
    const int w8 = t >> 5, lane = t & 31;
    const int lr = lane >> 2, lc = lane & 3;
    const int wm = w8 & 3, wn = w8 >> 2;

    float acc[2][4][4];
#pragma unroll
    for (int i = 0; i < 2; ++i)
#pragma unroll
        for (int j = 0; j < 4; ++j)
#pragma unroll
            for (int e = 0; e < 4; ++e) acc[i][j][e] = 0.f;

    const float* xb = x + (size_t)b * CC * NN;

    for (int k0 = 0; k0 < CC; k0 += 32) {
        __syncthreads();
        // A: x[b, k0..k0+31, m0..m0+127] -> As[m][k] (transpose)
#pragma unroll
        for (int r = 0; r < 4; ++r) {
            int idx = t + r * 256;
            int kk = idx >> 5, m4 = idx & 31;
            float4 v = *(const float4*)(xb + (size_t)(k0 + kk) * NN + m0 + m4 * 4);
            As[(m4 * 4 + 0) * 36 + kk] = tf32r(v.x);
            As[(m4 * 4 + 1) * 36 + kk] = tf32r(v.y);
            As[(m4 * 4 + 2) * 36 + kk] = tf32r(v.z);
            As[(m4 * 4 + 3) * 36 + kk] = tf32r(v.w);
        }
        // B: w[j0+j][k0..k0+31] -> Bs[j][k] (direct)
#pragma unroll
        for (int r = 0; r < 2; ++r) {
            int idx = t + r * 256;
            int j = idx >> 3, k4 = idx & 7;
            float4 v = *(const float4*)(w + (size_t)(j0 + j) * CC + k0 + k4 * 4);
            v.x = tf32r(v.x); v.y = tf32r(v.y); v.z = tf32r(v.z); v.w = tf32r(v.w);
            *(float4*)&Bs[j * 36 + k4 * 4] = v;
        }
        __syncthreads();
#pragma unroll
        for (int kb = 0; kb < 4; ++kb) {
            float af[2][4], bf[4][2];
#pragma unroll
            for (int mt = 0; mt < 2; ++mt) {
                int base = (wm * 32 + mt * 16 + lr) * 36 + kb * 8 + lc;
                af[mt][0] = As[base];
                af[mt][1] = As[base + 8 * 36];
                af[mt][2] = As[base + 4];
                af[mt][3] = As[base + 8 * 36 + 4];
            }
#pragma unroll
            for (int nb = 0; nb < 4; ++nb) {
                int bb = (wn * 32 + nb * 8 + lr) * 36 + kb * 8 + lc;
                bf[nb][0] = Bs[bb];
                bf[nb][1] = Bs[bb + 4];
            }
#pragma unroll
            for (int mt = 0; mt < 2; ++mt)
#pragma unroll
                for (int nb = 0; nb < 4; ++nb)
                    mma_tf32(acc[mt][nb], af[mt], bf[nb][0], bf[nb][1]);
        }
    }

    // epilogue: scatter with bias. which tensor constant per CTA (64 | 384).
    const int which = j0 / CC;
    float* dst = (which == 0) ? g_q : (which == 1) ? g_k : g_v;
#pragma unroll
    for (int mt = 0; mt < 2; ++mt) {
        int n1 = m0 + wm * 32 + mt * 16 + lr;
        int n2 = n1 + 8;
#pragma unroll
        for (int nb = 0; nb < 4; ++nb) {
            int jl = j0 + wn * 32 + nb * 8 + 2 * lc;
            int rem = jl - which * CC;
            int h = rem / HD;
            int d = rem - h * HD;            // even, so d+1 stays in-head
            float b0v = bias[jl], b1v = bias[jl + 1];
            size_t base = ((size_t)b * NH + h) * NN;
            *(float2*)&dst[(base + n1) * HD + d] =
                make_float2(acc[mt][nb][0] + b0v, acc[mt][nb][1] + b1v);
            *(float2*)&dst[(base + n2) * HD + d] =
                make_float2(acc[mt][nb][2] + b0v, acc[mt][nb][3] + b1v);
        }
    }
}

// ---------------------------------------------------------------------------
// L2-normalize rows of g_q and g_k. One warp per row.
// ---------------------------------------------------------------------------
__global__ __launch_bounds__(256) void l2norm_kernel() {
    const int NROWS = BB * NH * NN;
    int warp = (blockIdx.x * 256 + threadIdx.x) >> 5;
    int lane = threadIdx.x & 31;
    float* base = (warp < NROWS) ? g_q : g_k;
    int row = warp & (NROWS - 1);
    float* p = base + (size_t)row * HD;
    float e1 = p[lane];
    float e2 = (lane < 16) ? p[32 + lane] : 0.f;
    float ss = e1 * e1 + e2 * e2;
#pragma unroll
    for (int s = 16; s > 0; s >>= 1) ss += __shfl_xor_sync(0xffffffffu, ss, s);
    float inv = 1.0f / fmaxf(sqrtf(ss), 1e-12f);
    p[lane] = e1 * inv;
    if (lane < 16) p[32 + lane] = e2 * inv;
}

// ---------------------------------------------------------------------------
// Tensor-core flash attention via mma.sync tf32 (m16n8k8). (unchanged, R7)
// ---------------------------------------------------------------------------
#define KS_STRIDE 52
#define VS_STRIDE 72
#define PS_STRIDE 68
#define SM_VS_F   (64 * KS_STRIDE)
#define SM_PS_F   (SM_VS_F + 64 * VS_STRIDE)
#define ATTN_SMEM_F (SM_PS_F + 8 * 16 * PS_STRIDE)

__global__ __launch_bounds__(256) void attn_mma(const float* __restrict__ temp) {
    extern __shared__ float sm[];
    float* Ks = sm;
    float* Vs = sm + SM_VS_F;
    float* Ps = sm + SM_PS_F;

    const int t = threadIdx.x;
    const int w = t >> 5;
    const int lane = t & 31;
    const int lr = lane >> 2;
    const int lc = lane & 3;
    const int i0 = blockIdx.x * 128;
    const int bh = blockIdx.y;
    const int h  = bh & (NH - 1);
    const float* qg = g_q + (size_t)bh * NN * HD;
    const float* kg = g_k + (size_t)bh * NN * HD;
    const float* vg = g_v + (size_t)bh * NN * HD;
    const float tpr = temp[h];
    const float mterm = fabsf(tpr);

    for (int idx = t; idx < 128 * 12; idx += 256) {
        int r = idx / 12, c4 = idx % 12;
        float4 v = *(const float4*)(qg + (size_t)(i0 + r) * HD + c4 * 4);
        v.x = tf32r(v.x); v.y = tf32r(v.y); v.z = tf32r(v.z); v.w = tf32r(v.w);
        *(float4*)&sm[r * KS_STRIDE + c4 * 4] = v;
    }
    __syncthreads();

    float qf[6][4];
    {
        const int mr = w * 16 + lr;
#pragma unroll
        for (int kb = 0; kb < 6; ++kb) {
            qf[kb][0] = sm[mr * KS_STRIDE + kb * 8 + lc];
            qf[kb][1] = sm[(mr + 8) * KS_STRIDE + kb * 8 + lc];
            qf[kb][2] = sm[mr * KS_STRIDE + kb * 8 + lc + 4];
            qf[kb][3] = sm[(mr + 8) * KS_STRIDE + kb * 8 + lc + 4];
        }
    }

    float oacc[6][4];
#pragma unroll
    for (int i = 0; i < 6; ++i)
#pragma unroll
        for (int j = 0; j < 4; ++j) oacc[i][j] = 0.f;
    float rsum0 = 0.f, rsum1 = 0.f;
    float* Pw = Ps + w * 16 * PS_STRIDE;

    for (int kt = 0; kt < 16; ++kt) {
        const int k0 = kt * 64;
        __syncthreads();
        for (int idx = t; idx < 64 * 12; idx += 256) {
            int n = idx / 12, c4 = idx % 12;
            float4 v = *(const float4*)(kg + (size_t)(k0 + n) * HD + c4 * 4);
            v.x = tf32r(v.x); v.y = tf32r(v.y); v.z = tf32r(v.z); v.w = tf32r(v.w);
            *(float4*)&Ks[n * KS_STRIDE + c4 * 4] = v;
            float4 u = *(const float4*)(vg + (size_t)(k0 + n) * HD + c4 * 4);
            u.x = tf32r(u.x); u.y = tf32r(u.y); u.z = tf32r(u.z); u.w = tf32r(u.w);
            *(float4*)&Vs[n * VS_STRIDE + c4 * 4] = u;
        }
        __syncthreads();

        float sacc[8][4];
#pragma unroll
        for (int i = 0; i < 8; ++i)
#pragma unroll
            for (int j = 0; j < 4; ++j) sacc[i][j] = 0.f;
#pragma unroll
        for (int nb = 0; nb < 8; ++nb) {
            const float* kbase = Ks + (nb * 8 + lr) * KS_STRIDE + lc;
#pragma unroll
            for (int kb = 0; kb < 6; ++kb) {
                float b0 = kbase[kb * 8];
                float b1 = kbase[kb * 8 + 4];
                mma_tf32(sacc[nb], qf[kb], b0, b1);
            }
        }

#pragma unroll
        for (int nb = 0; nb < 8; ++nb) {
            float p0 = __expf(fmaf(sacc[nb][0], tpr, -mterm));
            float p1 = __expf(fmaf(sacc[nb][1], tpr, -mterm));
            float p2 = __expf(fmaf(sacc[nb][2], tpr, -mterm));
            float p3 = __expf(fmaf(sacc[nb][3], tpr, -mterm));
            rsum0 += p0 + p1;
            rsum1 += p2 + p3;
            *(float2*)&Pw[lr * PS_STRIDE + nb * 8 + 2 * lc] =
                make_float2(tf32r(p0), tf32r(p1));
            *(float2*)&Pw[(lr + 8) * PS_STRIDE + nb * 8 + 2 * lc] =
                make_float2(tf32r(p2), tf32r(p3));
        }
        __syncwarp();

#pragma unroll
        for (int kb2 = 0; kb2 < 8; ++kb2) {
            float af[4];
            af[0] = Pw[lr * PS_STRIDE + kb2 * 8 + lc];
            af[1] = Pw[(lr + 8) * PS_STRIDE + kb2 * 8 + lc];
            af[2] = Pw[lr * PS_STRIDE + kb2 * 8 + lc + 4];
            af[3] = Pw[(lr + 8) * PS_STRIDE + kb2 * 8 + lc + 4];
            const float* vb0 = Vs + (kb2 * 8 + lc) * VS_STRIDE + lr;
            const float* vb1 = Vs + (kb2 * 8 + lc + 4) * VS_STRIDE + lr;
#pragma unroll
            for (int nb2 = 0; nb2 < 6; ++nb2) {
                mma_tf32(oacc[nb2], af, vb0[nb2 * 8], vb1[nb2 * 8]);
            }
        }
    }

    rsum0 += __shfl_xor_sync(0xffffffffu, rsum0, 1);
    rsum0 += __shfl_xor_sync(0xffffffffu, rsum0, 2);
    rsum1 += __shfl_xor_sync(0xffffffffu, rsum1, 1);
    rsum1 += __shfl_xor_sync(0xffffffffu, rsum1, 2);
    const float inv0 = 1.0f / rsum0;
    const float inv1 = 1.0f / rsum1;
    const int b = bh >> 3;
    const int row0 = i0 + w * 16 + lr;
    float* o0 = g_o + ((size_t)b * NN + row0) * CC + h * HD;
    float* o1 = o0 + 8 * CC;
#pragma unroll
    for (int nb = 0; nb < 6; ++nb) {
        *(float2*)&o0[nb * 8 + 2 * lc] = make_float2(oacc[nb][0] * inv0, oacc[nb][1] * inv0);
        *(float2*)&o1[nb * 8 + 2 * lc] = make_float2(oacc[nb][2] * inv1, oacc[nb][3] * inv1);
    }
}

// ===========================================================================
// GEMM 2 (tensor core tf32): out[b,j,n] = sum_c g_o[b,n,c]*proj_w[j,c]+pb[j]
// Same tiling as qkv. Epilogue stages C through smem so stores along n are
// coalesced (direct store would be 4B-scattered with stride 4KB).
// Smem: Sm[8448]; As=Sm[0..4607], Bs=Sm[4608..6911], Cs aliases Sm (64x132).
// ===========================================================================
__global__ __launch_bounds__(256) void gemm_proj_tc(const float* __restrict__ w,
                                                    const float* __restrict__ bias,
                                                    float* __restrict__ out) {
    __shared__ float Sm[8448];
    float* As = Sm;
    float* Bs = Sm + 128 * 36;
    float* Cs = Sm;           // reused after compute

    const int b  = blockIdx.z;
    const int m0 = blockIdx.y * 128;
    const int j0 = blockIdx.x * 64;
    const int t  = threadIdx.x;
    const int w8 = t >> 5, lane = t & 31;
    const int lr = lane >> 2, lc = lane & 3;
    const int wm = w8 & 3, wn = w8 >> 2;

    float acc[2][4][4];
#pragma unroll
    for (int i = 0; i < 2; ++i)
#pragma unroll
        for (int j = 0; j < 4; ++j)
#pragma unroll
            for (int e = 0; e < 4; ++e) acc[i][j][e] = 0.f;

    const float* A = g_o + (size_t)b * NN * CC;

    for (int k0 = 0; k0 < CC; k0 += 32) {
        __syncthreads();
        // A: g_o[n][c] k-contiguous -> As[m][k] direct
#pragma unroll
        for (int r = 0; r < 4; ++r) {
            int idx = t + r * 256;
            int m = idx >> 3, k4 = idx & 7;
            float4 v = *(const float4*)(A + (size_t)(m0 + m) * CC + k0 + k4 * 4);
            v.x = tf32r(v.x); v.y = tf32r(v.y); v.z = tf32r(v.z); v.w = tf32r(v.w);
            *(float4*)&As[m * 36 + k4 * 4] = v;
        }
#pragma unroll
        for (int r = 0; r < 2; ++r) {
            int idx = t + r * 256;
            int j = idx >> 3, k4 = idx & 7;
            float4 v = *(const float4*)(w + (size_t)(j0 + j) * CC + k0 + k4 * 4);
            v.x = tf32r(v.x); v.y = tf32r(v.y); v.z = tf32r(v.z); v.w = tf32r(v.w);
            *(float4*)&Bs[j * 36 + k4 * 4] = v;
        }
        __syncthreads();
#pragma unroll
        for (int kb = 0; kb < 4; ++kb) {
            float af[2][4], bf[4][2];
#pragma unroll
            for (int mt = 0; mt < 2; ++mt) {
                int base = (wm * 32 + mt * 16 + lr) * 36 + kb * 8 + lc;
                af[mt][0] = As[base];
                af[mt][1] = As[base + 8 * 36];
                af[mt][2] = As[base + 4];
                af[mt][3] = As[base + 8 * 36 + 4];
            }
#pragma unroll
            for (int nb = 0; nb < 4; ++nb) {
                int bb = (wn * 32 + nb * 8 + lr) * 36 + kb * 8 + lc;
                bf[nb][0] = Bs[bb];
                bf[nb][1] = Bs[bb + 4];
            }
#pragma unroll
            for (int mt = 0; mt < 2; ++mt)
#pragma unroll
                for (int nb = 0; nb < 4; ++nb)
                    mma_tf32(acc[mt][nb], af[mt], bf[nb][0], bf[nb][1]);
        }
    }

    // stage C -> Cs[j][m] (stride 132), then coalesced store along n
    __syncthreads();
#pragma unroll
    for (int mt = 0; mt < 2; ++mt) {
        int m1 = wm * 32 + mt * 16 + lr;
        int m2 = m1 + 8;
#pragma unroll
        for (int nb = 0; nb < 4; ++nb) {
            int j = wn * 32 + nb * 8 + 2 * lc;
            Cs[j * 132 + m1]       = acc[mt][nb][0];
            Cs[(j + 1) * 132 + m1] = acc[mt][nb][1];
            Cs[j * 132 + m2]       = acc[mt][nb][2];
            Cs[(j + 1) * 132 + m2] = acc[mt][nb][3];
        }
    }
    __syncthreads();
#pragma unroll
    for (int r = 0; r < 8; ++r) {
        int idx = t + r * 256;
        int j = idx >> 5, m4 = idx & 31;
        float bj = bias[j0 + j];
        float4 v = *(float4*)&Cs[j * 132 + m4 * 4];
        v.x += bj; v.y += bj; v.z += bj; v.w += bj;
        *(float4*)(out + ((size_t)b * CC + j0 + j) * NN + m0 + m4 * 4) = v;
    }
}

// ===========================================================================
extern "C" void kernel_launch(void* const* d_in, const int* in_sizes, int n_in,
                              void* d_out, int out_size) {
    const float* x      = (const float*)d_in[0];
    const float* temp   = (const float*)d_in[1];
    const float* qkv_w  = (const float*)d_in[2];
    const float* qkv_b  = (const float*)d_in[3];
    const float* proj_w = (const float*)d_in[4];
    const float* proj_b = (const float*)d_in[5];
    float* out = (float*)d_out;

    static const int ATTN_SMEM = ATTN_SMEM_F * 4;   // 66560 bytes
    cudaFuncSetAttribute(attn_mma, cudaFuncAttributeMaxDynamicSharedMemorySize,
                         ATTN_SMEM);

    gemm_qkv_tc<<<dim3(18, 8, BB), 256>>>(x, qkv_w, qkv_b);
    l2norm_kernel<<<32768, 256>>>();
    attn_mma<<<dim3(8, BB * NH), 256, ATTN_SMEM>>>(temp);
    gemm_proj_tc<<<dim3(6, 8, BB), 256>>>(proj_w, proj_b, out);
}

// round 10
// speedup vs baseline: 6.2649x; 1.4774x over previous
#include <cuda_runtime.h>
#include <cstdint>

#define NH 8
#define HD 48
#define CC 384
#define NN 1024
#define BB 16

// Scratch (device globals; no allocations allowed)
__device__ float g_q[BB*NH*NN*HD];
__device__ float g_k[BB*NH*NN*HD];
__device__ float g_v[BB*NH*NN*HD];
__device__ float g_o[BB*NN*CC];

// ---------------------------------------------------------------------------
// tf32 helpers (sm_80+ baseline ISA)
// ---------------------------------------------------------------------------
__device__ __forceinline__ float tf32r(float x) {
    uint32_t r;
    asm("cvt.rna.tf32.f32 %0, %1;" : "=r"(r) : "f"(x));
    return __uint_as_float(r);
}
__device__ __forceinline__ void mma_tf32(float* acc, const float* a, float b0, float b1) {
    asm volatile(
        "mma.sync.aligned.m16n8k8.row.col.f32.tf32.tf32.f32 "
        "{%0,%1,%2,%3}, {%4,%5,%6,%7}, {%8,%9}, {%0,%1,%2,%3};"
        : "+f"(acc[0]), "+f"(acc[1]), "+f"(acc[2]), "+f"(acc[3])
        : "r"(__float_as_uint(a[0])), "r"(__float_as_uint(a[1])),
          "r"(__float_as_uint(a[2])), "r"(__float_as_uint(a[3])),
          "r"(__float_as_uint(b0)),  "r"(__float_as_uint(b1)));
}

// ===========================================================================
// GEMM 1 (tf32 TC, transpose-free): C[j][n] = sum_k w[j][k] * x[b][k][n]
// CTA tile: M(j)=128, N(n)=128, K=32. 8 warps as 2(m) x 4(n); warp 64x32.
// A = w staged [j][k] stride 36 (direct float4, frag banks 4*lr+lc distinct).
// B = x staged [k][n] stride 136 (direct float4, frag banks 8*lc+lr distinct).
// Epilogue scatters into g_q/g_k/g_v; 128-wide j tiles never straddle q/k/v.
// ===========================================================================
__global__ __launch_bounds__(256) void gemm_qkv_tc(const float* __restrict__ x,
                                                   const float* __restrict__ w,
                                                   const float* __restrict__ bias) {
    __shared__ float As[128 * 36];   // [j][k]
    __shared__ float Bs[32 * 136];   // [k][n]
    const int b  = blockIdx.z;
    const int j0 = blockIdx.x * 128;
    const int n0 = blockIdx.y * 128;
    const int t  = threadIdx.x;
    const int w8 = t >> 5, lane = t & 31;
    const int lr = lane >> 2, lc = lane & 3;
    const int wm = w8 & 1, wn = w8 >> 1;      // 2 x 4 warp grid

    float acc[4][4][4];
#pragma unroll
    for (int i = 0; i < 4; ++i)
#pragma unroll
        for (int j = 0; j < 4; ++j)
#pragma unroll
            for (int e = 0; e < 4; ++e) acc[i][j][e] = 0.f;

    const float* xb = x + (size_t)b * CC * NN;

    for (int k0 = 0; k0 < CC; k0 += 32) {
        __syncthreads();
        // A: w[j0+j][k0..k0+31] -> As[j][k]  (direct, conflict-free)
#pragma unroll
        for (int r = 0; r < 4; ++r) {
            int idx = t + r * 256;
            int j = idx >> 3, k4 = idx & 7;
            float4 v = *(const float4*)(w + (size_t)(j0 + j) * CC + k0 + k4 * 4);
            v.x = tf32r(v.x); v.y = tf32r(v.y); v.z = tf32r(v.z); v.w = tf32r(v.w);
            *(float4*)&As[j * 36 + k4 * 4] = v;
        }
        // B: x[k0+kk][n0..n0+127] -> Bs[k][n]  (direct, conflict-free)
#pragma unroll
        for (int r = 0; r < 4; ++r) {
            int idx = t + r * 256;
            int kk = idx >> 5, m4 = idx & 31;
            float4 v = *(const float4*)(xb + (size_t)(k0 + kk) * NN + n0 + m4 * 4);
            v.x = tf32r(v.x); v.y = tf32r(v.y); v.z = tf32r(v.z); v.w = tf32r(v.w);
            *(float4*)&Bs[kk * 136 + m4 * 4] = v;
        }
        __syncthreads();
#pragma unroll
        for (int kb = 0; kb < 4; ++kb) {
            float af[4][4], bf[4][2];
#pragma unroll
            for (int mt = 0; mt < 4; ++mt) {
                int base = (wm * 64 + mt * 16 + lr) * 36 + kb * 8 + lc;
                af[mt][0] = As[base];
                af[mt][1] = As[base + 8 * 36];
                af[mt][2] = As[base + 4];
                af[mt][3] = As[base + 8 * 36 + 4];
            }
#pragma unroll
            for (int nb = 0; nb < 4; ++nb) {
                int nn = wn * 32 + nb * 8 + lr;
                bf[nb][0] = Bs[(kb * 8 + lc) * 136 + nn];
                bf[nb][1] = Bs[(kb * 8 + lc + 4) * 136 + nn];
            }
#pragma unroll
            for (int mt = 0; mt < 4; ++mt)
#pragma unroll
                for (int nb = 0; nb < 4; ++nb)
                    mma_tf32(acc[mt][nb], af[mt], bf[nb][0], bf[nb][1]);
        }
    }

    // epilogue: C[j][n] scatter. which tensor constant per CTA (128 | 384).
    const int which = j0 / CC;
    float* dst = (which == 0) ? g_q : (which == 1) ? g_k : g_v;
#pragma unroll
    for (int mt = 0; mt < 4; ++mt) {
        int j1 = j0 + wm * 64 + mt * 16 + lr;
        int j2 = j1 + 8;
        int rem1 = j1 - which * CC;
        int h1 = rem1 / HD, d1 = rem1 - h1 * HD;
        int rem2 = j2 - which * CC;
        int h2 = rem2 / HD, d2 = rem2 - h2 * HD;
        float bj1 = bias[j1], bj2 = bias[j2];
        size_t base1 = ((size_t)b * NH + h1) * NN;
        size_t base2 = ((size_t)b * NH + h2) * NN;
#pragma unroll
        for (int nb = 0; nb < 4; ++nb) {
            int n = n0 + wn * 32 + nb * 8 + 2 * lc;
            dst[(base1 + n)     * HD + d1] = acc[mt][nb][0] + bj1;
            dst[(base1 + n + 1) * HD + d1] = acc[mt][nb][1] + bj1;
            dst[(base2 + n)     * HD + d2] = acc[mt][nb][2] + bj2;
            dst[(base2 + n + 1) * HD + d2] = acc[mt][nb][3] + bj2;
        }
    }
}

// ---------------------------------------------------------------------------
// L2-normalize rows of g_q and g_k. One warp per row.
// ---------------------------------------------------------------------------
__global__ __launch_bounds__(256) void l2norm_kernel() {
    const int NROWS = BB * NH * NN;
    int warp = (blockIdx.x * 256 + threadIdx.x) >> 5;
    int lane = threadIdx.x & 31;
    float* base = (warp < NROWS) ? g_q : g_k;
    int row = warp & (NROWS - 1);
    float* p = base + (size_t)row * HD;
    float e1 = p[lane];
    float e2 = (lane < 16) ? p[32 + lane] : 0.f;
    float ss = e1 * e1 + e2 * e2;
#pragma unroll
    for (int s = 16; s > 0; s >>= 1) ss += __shfl_xor_sync(0xffffffffu, ss, s);
    float inv = 1.0f / fmaxf(sqrtf(ss), 1e-12f);
    p[lane] = e1 * inv;
    if (lane < 16) p[32 + lane] = e2 * inv;
}

// ---------------------------------------------------------------------------
// Tensor-core flash attention via mma.sync tf32 (m16n8k8). (unchanged, R7)
// ---------------------------------------------------------------------------
#define KS_STRIDE 52
#define VS_STRIDE 72
#define PS_STRIDE 68
#define SM_VS_F   (64 * KS_STRIDE)
#define SM_PS_F   (SM_VS_F + 64 * VS_STRIDE)
#define ATTN_SMEM_F (SM_PS_F + 8 * 16 * PS_STRIDE)

__global__ __launch_bounds__(256) void attn_mma(const float* __restrict__ temp) {
    extern __shared__ float sm[];
    float* Ks = sm;
    float* Vs = sm + SM_VS_F;
    float* Ps = sm + SM_PS_F;

    const int t = threadIdx.x;
    const int w = t >> 5;
    const int lane = t & 31;
    const int lr = lane >> 2;
    const int lc = lane & 3;
    const int i0 = blockIdx.x * 128;
    const int bh = blockIdx.y;
    const int h  = bh & (NH - 1);
    const float* qg = g_q + (size_t)bh * NN * HD;
    const float* kg = g_k + (size_t)bh * NN * HD;
    const float* vg = g_v + (size_t)bh * NN * HD;
    const float tpr = temp[h];
    const float mterm = fabsf(tpr);

    for (int idx = t; idx < 128 * 12; idx += 256) {
        int r = idx / 12, c4 = idx % 12;
        float4 v = *(const float4*)(qg + (size_t)(i0 + r) * HD + c4 * 4);
        v.x = tf32r(v.x); v.y = tf32r(v.y); v.z = tf32r(v.z); v.w = tf32r(v.w);
        *(float4*)&sm[r * KS_STRIDE + c4 * 4] = v;
    }
    __syncthreads();

    float qf[6][4];
    {
        const int mr = w * 16 + lr;
#pragma unroll
        for (int kb = 0; kb < 6; ++kb) {
            qf[kb][0] = sm[mr * KS_STRIDE + kb * 8 + lc];
            qf[kb][1] = sm[(mr + 8) * KS_STRIDE + kb * 8 + lc];
            qf[kb][2] = sm[mr * KS_STRIDE + kb * 8 + lc + 4];
            qf[kb][3] = sm[(mr + 8) * KS_STRIDE + kb * 8 + lc + 4];
        }
    }

    float oacc[6][4];
#pragma unroll
    for (int i = 0; i < 6; ++i)
#pragma unroll
        for (int j = 0; j < 4; ++j) oacc[i][j] = 0.f;
    float rsum0 = 0.f, rsum1 = 0.f;
    float* Pw = Ps + w * 16 * PS_STRIDE;

    for (int kt = 0; kt < 16; ++kt) {
        const int k0 = kt * 64;
        __syncthreads();
        for (int idx = t; idx < 64 * 12; idx += 256) {
            int n = idx / 12, c4 = idx % 12;
            float4 v = *(const float4*)(kg + (size_t)(k0 + n) * HD + c4 * 4);
            v.x = tf32r(v.x); v.y = tf32r(v.y); v.z = tf32r(v.z); v.w = tf32r(v.w);
            *(float4*)&Ks[n * KS_STRIDE + c4 * 4] = v;
            float4 u = *(const float4*)(vg + (size_t)(k0 + n) * HD + c4 * 4);
            u.x = tf32r(u.x); u.y = tf32r(u.y); u.z = tf32r(u.z); u.w = tf32r(u.w);
            *(float4*)&Vs[n * VS_STRIDE + c4 * 4] = u;
        }
        __syncthreads();

        float sacc[8][4];
#pragma unroll
        for (int i = 0; i < 8; ++i)
#pragma unroll
            for (int j = 0; j < 4; ++j) sacc[i][j] = 0.f;
#pragma unroll
        for (int nb = 0; nb < 8; ++nb) {
            const float* kbase = Ks + (nb * 8 + lr) * KS_STRIDE + lc;
#pragma unroll
            for (int kb = 0; kb < 6; ++kb) {
                float b0 = kbase[kb * 8];
                float b1 = kbase[kb * 8 + 4];
                mma_tf32(sacc[nb], qf[kb], b0, b1);
            }
        }

#pragma unroll
        for (int nb = 0; nb < 8; ++nb) {
            float p0 = __expf(fmaf(sacc[nb][0], tpr, -mterm));
            float p1 = __expf(fmaf(sacc[nb][1], tpr, -mterm));
            float p2 = __expf(fmaf(sacc[nb][2], tpr, -mterm));
            float p3 = __expf(fmaf(sacc[nb][3], tpr, -mterm));
            rsum0 += p0 + p1;
            rsum1 += p2 + p3;
            *(float2*)&Pw[lr * PS_STRIDE + nb * 8 + 2 * lc] =
                make_float2(tf32r(p0), tf32r(p1));
            *(float2*)&Pw[(lr + 8) * PS_STRIDE + nb * 8 + 2 * lc] =
                make_float2(tf32r(p2), tf32r(p3));
        }
        __syncwarp();

#pragma unroll
        for (int kb2 = 0; kb2 < 8; ++kb2) {
            float af[4];
            af[0] = Pw[lr * PS_STRIDE + kb2 * 8 + lc];
            af[1] = Pw[(lr + 8) * PS_STRIDE + kb2 * 8 + lc];
            af[2] = Pw[lr * PS_STRIDE + kb2 * 8 + lc + 4];
            af[3] = Pw[(lr + 8) * PS_STRIDE + kb2 * 8 + lc + 4];
            const float* vb0 = Vs + (kb2 * 8 + lc) * VS_STRIDE + lr;
            const float* vb1 = Vs + (kb2 * 8 + lc + 4) * VS_STRIDE + lr;
#pragma unroll
            for (int nb2 = 0; nb2 < 6; ++nb2) {
                mma_tf32(oacc[nb2], af, vb0[nb2 * 8], vb1[nb2 * 8]);
            }
        }
    }

    rsum0 += __shfl_xor_sync(0xffffffffu, rsum0, 1);
    rsum0 += __shfl_xor_sync(0xffffffffu, rsum0, 2);
    rsum1 += __shfl_xor_sync(0xffffffffu, rsum1, 1);
    rsum1 += __shfl_xor_sync(0xffffffffu, rsum1, 2);
    const float inv0 = 1.0f / rsum0;
    const float inv1 = 1.0f / rsum1;
    const int b = bh >> 3;
    const int row0 = i0 + w * 16 + lr;
    float* o0 = g_o + ((size_t)b * NN + row0) * CC + h * HD;
    float* o1 = o0 + 8 * CC;
#pragma unroll
    for (int nb = 0; nb < 6; ++nb) {
        *(float2*)&o0[nb * 8 + 2 * lc] = make_float2(oacc[nb][0] * inv0, oacc[nb][1] * inv0);
        *(float2*)&o1[nb * 8 + 2 * lc] = make_float2(oacc[nb][2] * inv1, oacc[nb][3] * inv1);
    }
}

// ===========================================================================
// GEMM 2 (tf32 TC): out[b,j,n] = sum_c g_o[b,n,c]*proj_w[j,c]+pb[j] (R8, ok)
// ===========================================================================
__global__ __launch_bounds__(256) void gemm_proj_tc(const float* __restrict__ w,
                                                    const float* __restrict__ bias,
                                                    float* __restrict__ out) {
    __shared__ float Sm[8448];
    float* As = Sm;
    float* Bs = Sm + 128 * 36;
    float* Cs = Sm;

    const int b  = blockIdx.z;
    const int m0 = blockIdx.y * 128;
    const int j0 = blockIdx.x * 64;
    const int t  = threadIdx.x;
    const int w8 = t >> 5, lane = t & 31;
    const int lr = lane >> 2, lc = lane & 3;
    const int wm = w8 & 3, wn = w8 >> 2;

    float acc[2][4][4];
#pragma unroll
    for (int i = 0; i < 2; ++i)
#pragma unroll
        for (int j = 0; j < 4; ++j)
#pragma unroll
            for (int e = 0; e < 4; ++e) acc[i][j][e] = 0.f;

    const float* A = g_o + (size_t)b * NN * CC;

    for (int k0 = 0; k0 < CC; k0 += 32) {
        __syncthreads();
#pragma unroll
        for (int r = 0; r < 4; ++r) {
            int idx = t + r * 256;
            int m = idx >> 3, k4 = idx & 7;
            float4 v = *(const float4*)(A + (size_t)(m0 + m) * CC + k0 + k4 * 4);
            v.x = tf32r(v.x); v.y = tf32r(v.y); v.z = tf32r(v.z); v.w = tf32r(v.w);
            *(float4*)&As[m * 36 + k4 * 4] = v;
        }
#pragma unroll
        for (int r = 0; r < 2; ++r) {
            int idx = t + r * 256;
            int j = idx >> 3, k4 = idx & 7;
            float4 v = *(const float4*)(w + (size_t)(j0 + j) * CC + k0 + k4 * 4);
            v.x = tf32r(v.x); v.y = tf32r(v.y); v.z = tf32r(v.z); v.w = tf32r(v.w);
            *(float4*)&Bs[j * 36 + k4 * 4] = v;
        }
        __syncthreads();
#pragma unroll
        for (int kb = 0; kb < 4; ++kb) {
            float af[2][4], bf[4][2];
#pragma unroll
            for (int mt = 0; mt < 2; ++mt) {
                int base = (wm * 32 + mt * 16 + lr) * 36 + kb * 8 + lc;
                af[mt][0] = As[base];
                af[mt][1] = As[base + 8 * 36];
                af[mt][2] = As[base + 4];
                af[mt][3] = As[base + 8 * 36 + 4];
            }
#pragma unroll
            for (int nb = 0; nb < 4; ++nb) {
                int bb = (wn * 32 + nb * 8 + lr) * 36 + kb * 8 + lc;
                bf[nb][0] = Bs[bb];
                bf[nb][1] = Bs[bb + 4];
            }
#pragma unroll
            for (int mt = 0; mt < 2; ++mt)
#pragma unroll
                for (int nb = 0; nb < 4; ++nb)
                    mma_tf32(acc[mt][nb], af[mt], bf[nb][0], bf[nb][1]);
        }
    }

    __syncthreads();
#pragma unroll
    for (int mt = 0; mt < 2; ++mt) {
        int m1 = wm * 32 + mt * 16 + lr;
        int m2 = m1 + 8;
#pragma unroll
        for (int nb = 0; nb < 4; ++nb) {
            int j = wn * 32 + nb * 8 + 2 * lc;
            Cs[j * 132 + m1]       = acc[mt][nb][0];
            Cs[(j + 1) * 132 + m1] = acc[mt][nb][1];
            Cs[j * 132 + m2]       = acc[mt][nb][2];
            Cs[(j + 1) * 132 + m2] = acc[mt][nb][3];
        }
    }
    __syncthreads();
#pragma unroll
    for (int r = 0; r < 8; ++r) {
        int idx = t + r * 256;
        int j = idx >> 5, m4 = idx & 31;
        float bj = bias[j0 + j];
        float4 v = *(float4*)&Cs[j * 132 + m4 * 4];
        v.x += bj; v.y += bj; v.z += bj; v.w += bj;
        *(float4*)(out + ((size_t)b * CC + j0 + j) * NN + m0 + m4 * 4) = v;
    }
}

// ===========================================================================
extern "C" void kernel_launch(void* const* d_in, const int* in_sizes, int n_in,
                              void* d_out, int out_size) {
    const float* x      = (const float*)d_in[0];
    const float* temp   = (const float*)d_in[1];
    const float* qkv_w  = (const float*)d_in[2];
    const float* qkv_b  = (const float*)d_in[3];
    const float* proj_w = (const float*)d_in[4];
    const float* proj_b = (const float*)d_in[5];
    float* out = (float*)d_out;

    static const int ATTN_SMEM = ATTN_SMEM_F * 4;   // 66560 bytes
    cudaFuncSetAttribute(attn_mma, cudaFuncAttributeMaxDynamicSharedMemorySize,
                         ATTN_SMEM);

    gemm_qkv_tc<<<dim3(9, 8, BB), 256>>>(x, qkv_w, qkv_b);
    l2norm_kernel<<<32768, 256>>>();
    attn_mma<<<dim3(8, BB * NH), 256, ATTN_SMEM>>>(temp);
    gemm_proj_tc<<<dim3(6, 8, BB), 256>>>(proj_w, proj_b, out);
}

// round 11
// speedup vs baseline: 7.2147x; 1.1516x over previous
#include <cuda_runtime.h>
#include <cstdint>

#define NH 8
#define HD 48
#define CC 384
#define NN 1024
#define BB 16

// Scratch (device globals; no allocations allowed)
__device__ float g_q[BB*NH*NN*HD];
__device__ float g_k[BB*NH*NN*HD];
__device__ float g_v[BB*NH*NN*HD];
__device__ float g_o[BB*NN*CC];

// ---------------------------------------------------------------------------
// tf32 helpers (sm_80+ baseline ISA)
// ---------------------------------------------------------------------------
__device__ __forceinline__ float tf32r(float x) {
    uint32_t r;
    asm("cvt.rna.tf32.f32 %0, %1;" : "=r"(r) : "f"(x));
    return __uint_as_float(r);
}
__device__ __forceinline__ void mma_tf32(float* acc, const float* a, float b0, float b1) {
    asm volatile(
        "mma.sync.aligned.m16n8k8.row.col.f32.tf32.tf32.f32 "
        "{%0,%1,%2,%3}, {%4,%5,%6,%7}, {%8,%9}, {%0,%1,%2,%3};"
        : "+f"(acc[0]), "+f"(acc[1]), "+f"(acc[2]), "+f"(acc[3])
        : "r"(__float_as_uint(a[0])), "r"(__float_as_uint(a[1])),
          "r"(__float_as_uint(a[2])), "r"(__float_as_uint(a[3])),
          "r"(__float_as_uint(b0)),  "r"(__float_as_uint(b1)));
}

// ===========================================================================
// GEMM 1 (tf32 TC, transpose-free): C[j][n] = sum_k w[j][k] * x[b][k][n]
// (unchanged from R10 — 87us, ~167 TF/s)
// ===========================================================================
__global__ __launch_bounds__(256) void gemm_qkv_tc(const float* __restrict__ x,
                                                   const float* __restrict__ w,
                                                   const float* __restrict__ bias) {
    __shared__ float As[128 * 36];   // [j][k]
    __shared__ float Bs[32 * 136];   // [k][n]
    const int b  = blockIdx.z;
    const int j0 = blockIdx.x * 128;
    const int n0 = blockIdx.y * 128;
    const int t  = threadIdx.x;
    const int w8 = t >> 5, lane = t & 31;
    const int lr = lane >> 2, lc = lane & 3;
    const int wm = w8 & 1, wn = w8 >> 1;

    float acc[4][4][4];
#pragma unroll
    for (int i = 0; i < 4; ++i)
#pragma unroll
        for (int j = 0; j < 4; ++j)
#pragma unroll
            for (int e = 0; e < 4; ++e) acc[i][j][e] = 0.f;

    const float* xb = x + (size_t)b * CC * NN;

    for (int k0 = 0; k0 < CC; k0 += 32) {
        __syncthreads();
#pragma unroll
        for (int r = 0; r < 4; ++r) {
            int idx = t + r * 256;
            int j = idx >> 3, k4 = idx & 7;
            float4 v = *(const float4*)(w + (size_t)(j0 + j) * CC + k0 + k4 * 4);
            v.x = tf32r(v.x); v.y = tf32r(v.y); v.z = tf32r(v.z); v.w = tf32r(v.w);
            *(float4*)&As[j * 36 + k4 * 4] = v;
        }
#pragma unroll
        for (int r = 0; r < 4; ++r) {
            int idx = t + r * 256;
            int kk = idx >> 5, m4 = idx & 31;
            float4 v = *(const float4*)(xb + (size_t)(k0 + kk) * NN + n0 + m4 * 4);
            v.x = tf32r(v.x); v.y = tf32r(v.y); v.z = tf32r(v.z); v.w = tf32r(v.w);
            *(float4*)&Bs[kk * 136 + m4 * 4] = v;
        }
        __syncthreads();
#pragma unroll
        for (int kb = 0; kb < 4; ++kb) {
            float af[4][4], bf[4][2];
#pragma unroll
            for (int mt = 0; mt < 4; ++mt) {
                int base = (wm * 64 + mt * 16 + lr) * 36 + kb * 8 + lc;
                af[mt][0] = As[base];
                af[mt][1] = As[base + 8 * 36];
                af[mt][2] = As[base + 4];
                af[mt][3] = As[base + 8 * 36 + 4];
            }
#pragma unroll
            for (int nb = 0; nb < 4; ++nb) {
                int nn = wn * 32 + nb * 8 + lr;
                bf[nb][0] = Bs[(kb * 8 + lc) * 136 + nn];
                bf[nb][1] = Bs[(kb * 8 + lc + 4) * 136 + nn];
            }
#pragma unroll
            for (int mt = 0; mt < 4; ++mt)
#pragma unroll
                for (int nb = 0; nb < 4; ++nb)
                    mma_tf32(acc[mt][nb], af[mt], bf[nb][0], bf[nb][1]);
        }
    }

    const int which = j0 / CC;
    float* dst = (which == 0) ? g_q : (which == 1) ? g_k : g_v;
#pragma unroll
    for (int mt = 0; mt < 4; ++mt) {
        int j1 = j0 + wm * 64 + mt * 16 + lr;
        int j2 = j1 + 8;
        int rem1 = j1 - which * CC;
        int h1 = rem1 / HD, d1 = rem1 - h1 * HD;
        int rem2 = j2 - which * CC;
        int h2 = rem2 / HD, d2 = rem2 - h2 * HD;
        float bj1 = bias[j1], bj2 = bias[j2];
        size_t base1 = ((size_t)b * NH + h1) * NN;
        size_t base2 = ((size_t)b * NH + h2) * NN;
#pragma unroll
        for (int nb = 0; nb < 4; ++nb) {
            int n = n0 + wn * 32 + nb * 8 + 2 * lc;
            dst[(base1 + n)     * HD + d1] = acc[mt][nb][0] + bj1;
            dst[(base1 + n + 1) * HD + d1] = acc[mt][nb][1] + bj1;
            dst[(base2 + n)     * HD + d2] = acc[mt][nb][2] + bj2;
            dst[(base2 + n + 1) * HD + d2] = acc[mt][nb][3] + bj2;
        }
    }
}

// ---------------------------------------------------------------------------
// L2-normalize rows of g_q and g_k. One warp per row.
// ---------------------------------------------------------------------------
__global__ __launch_bounds__(256) void l2norm_kernel() {
    const int NROWS = BB * NH * NN;
    int warp = (blockIdx.x * 256 + threadIdx.x) >> 5;
    int lane = threadIdx.x & 31;
    float* base = (warp < NROWS) ? g_q : g_k;
    int row = warp & (NROWS - 1);
    float* p = base + (size_t)row * HD;
    float e1 = p[lane];
    float e2 = (lane < 16) ? p[32 + lane] : 0.f;
    float ss = e1 * e1 + e2 * e2;
#pragma unroll
    for (int s = 16; s > 0; s >>= 1) ss += __shfl_xor_sync(0xffffffffu, ss, s);
    float inv = 1.0f / fmaxf(sqrtf(ss), 1e-12f);
    p[lane] = e1 * inv;
    if (lane < 16) p[32 + lane] = e2 * inv;
}

// ---------------------------------------------------------------------------
// Tensor-core flash attention, tf32 mma.sync.
// R11: register prefetch of next K/V tile (loads overlap mma phase) and
// 2 CTAs/SM (__launch_bounds__(256,2)); S accumulators split in two halves
// to fit the 128-reg cap. Math identical to R7/R10.
// ---------------------------------------------------------------------------
#define KS_STRIDE 52
#define VS_STRIDE 72
#define PS_STRIDE 68
#define SM_VS_F   (64 * KS_STRIDE)
#define SM_PS_F   (SM_VS_F + 64 * VS_STRIDE)
#define ATTN_SMEM_F (SM_PS_F + 8 * 16 * PS_STRIDE)

__global__ __launch_bounds__(256, 2) void attn_mma(const float* __restrict__ temp) {
    extern __shared__ float sm[];
    float* Ks = sm;
    float* Vs = sm + SM_VS_F;
    float* Ps = sm + SM_PS_F;

    const int t = threadIdx.x;
    const int w = t >> 5;
    const int lane = t & 31;
    const int lr = lane >> 2;
    const int lc = lane & 3;
    const int i0 = blockIdx.x * 128;
    const int bh = blockIdx.y;
    const int h  = bh & (NH - 1);
    const float* qg = g_q + (size_t)bh * NN * HD;
    const float* kg = g_k + (size_t)bh * NN * HD;
    const float* vg = g_v + (size_t)bh * NN * HD;
    const float tpr = temp[h];
    const float mterm = fabsf(tpr);

    // stage Q via Ks region, extract persistent fragments
    for (int idx = t; idx < 128 * 12; idx += 256) {
        int r = idx / 12, c4 = idx % 12;
        float4 v = *(const float4*)(qg + (size_t)(i0 + r) * HD + c4 * 4);
        v.x = tf32r(v.x); v.y = tf32r(v.y); v.z = tf32r(v.z); v.w = tf32r(v.w);
        *(float4*)&sm[r * KS_STRIDE + c4 * 4] = v;
    }
    __syncthreads();

    float qf[6][4];
    {
        const int mr = w * 16 + lr;
#pragma unroll
        for (int kb = 0; kb < 6; ++kb) {
            qf[kb][0] = sm[mr * KS_STRIDE + kb * 8 + lc];
            qf[kb][1] = sm[(mr + 8) * KS_STRIDE + kb * 8 + lc];
            qf[kb][2] = sm[mr * KS_STRIDE + kb * 8 + lc + 4];
            qf[kb][3] = sm[(mr + 8) * KS_STRIDE + kb * 8 + lc + 4];
        }
    }

    float oacc[6][4];
#pragma unroll
    for (int i = 0; i < 6; ++i)
#pragma unroll
        for (int j = 0; j < 4; ++j) oacc[i][j] = 0.f;
    float rsum0 = 0.f, rsum1 = 0.f;
    float* Pw = Ps + w * 16 * PS_STRIDE;

    // prefetch tile 0 into registers
    float4 kpre[3], vpre[3];
#pragma unroll
    for (int r = 0; r < 3; ++r) {
        int idx = t + r * 256;
        int n = idx / 12, c4 = idx % 12;
        kpre[r] = *(const float4*)(kg + (size_t)n * HD + c4 * 4);
        vpre[r] = *(const float4*)(vg + (size_t)n * HD + c4 * 4);
    }

    for (int kt = 0; kt < 16; ++kt) {
        __syncthreads();   // prior compute (or Q-frag extraction) done
        // store prefetched tile to smem (tf32-rounded)
#pragma unroll
        for (int r = 0; r < 3; ++r) {
            int idx = t + r * 256;
            int n = idx / 12, c4 = idx % 12;
            float4 v = kpre[r];
            v.x = tf32r(v.x); v.y = tf32r(v.y); v.z = tf32r(v.z); v.w = tf32r(v.w);
            *(float4*)&Ks[n * KS_STRIDE + c4 * 4] = v;
            float4 u = vpre[r];
            u.x = tf32r(u.x); u.y = tf32r(u.y); u.z = tf32r(u.z); u.w = tf32r(u.w);
            *(float4*)&Vs[n * VS_STRIDE + c4 * 4] = u;
        }
        // issue next tile's loads; they complete under the mma phase
        if (kt < 15) {
            const int k1 = (kt + 1) * 64;
#pragma unroll
            for (int r = 0; r < 3; ++r) {
                int idx = t + r * 256;
                int n = idx / 12, c4 = idx % 12;
                kpre[r] = *(const float4*)(kg + (size_t)(k1 + n) * HD + c4 * 4);
                vpre[r] = *(const float4*)(vg + (size_t)(k1 + n) * HD + c4 * 4);
            }
        }
        __syncthreads();

        // ---- S = Q.K^T + softmax, two halves of 4 n-blocks ----
#pragma unroll
        for (int half = 0; half < 2; ++half) {
            float sacc[4][4];
#pragma unroll
            for (int i = 0; i < 4; ++i)
#pragma unroll
                for (int j = 0; j < 4; ++j) sacc[i][j] = 0.f;
#pragma unroll
            for (int nb4 = 0; nb4 < 4; ++nb4) {
                const int nb = half * 4 + nb4;
                const float* kbase = Ks + (nb * 8 + lr) * KS_STRIDE + lc;
#pragma unroll
                for (int kb = 0; kb < 6; ++kb) {
                    float b0 = kbase[kb * 8];
                    float b1 = kbase[kb * 8 + 4];
                    mma_tf32(sacc[nb4], qf[kb], b0, b1);
                }
            }
#pragma unroll
            for (int nb4 = 0; nb4 < 4; ++nb4) {
                const int nb = half * 4 + nb4;
                float p0 = __expf(fmaf(sacc[nb4][0], tpr, -mterm));
                float p1 = __expf(fmaf(sacc[nb4][1], tpr, -mterm));
                float p2 = __expf(fmaf(sacc[nb4][2], tpr, -mterm));
                float p3 = __expf(fmaf(sacc[nb4][3], tpr, -mterm));
                rsum0 += p0 + p1;
                rsum1 += p2 + p3;
                *(float2*)&Pw[lr * PS_STRIDE + nb * 8 + 2 * lc] =
                    make_float2(tf32r(p0), tf32r(p1));
                *(float2*)&Pw[(lr + 8) * PS_STRIDE + nb * 8 + 2 * lc] =
                    make_float2(tf32r(p2), tf32r(p3));
            }
        }
        __syncwarp();

        // ---- O += P.V ----
#pragma unroll
        for (int kb2 = 0; kb2 < 8; ++kb2) {
            float af[4];
            af[0] = Pw[lr * PS_STRIDE + kb2 * 8 + lc];
            af[1] = Pw[(lr + 8) * PS_STRIDE + kb2 * 8 + lc];
            af[2] = Pw[lr * PS_STRIDE + kb2 * 8 + lc + 4];
            af[3] = Pw[(lr + 8) * PS_STRIDE + kb2 * 8 + lc + 4];
            const float* vb0 = Vs + (kb2 * 8 + lc) * VS_STRIDE + lr;
            const float* vb1 = Vs + (kb2 * 8 + lc + 4) * VS_STRIDE + lr;
#pragma unroll
            for (int nb2 = 0; nb2 < 6; ++nb2) {
                mma_tf32(oacc[nb2], af, vb0[nb2 * 8], vb1[nb2 * 8]);
            }
        }
    }

    rsum0 += __shfl_xor_sync(0xffffffffu, rsum0, 1);
    rsum0 += __shfl_xor_sync(0xffffffffu, rsum0, 2);
    rsum1 += __shfl_xor_sync(0xffffffffu, rsum1, 1);
    rsum1 += __shfl_xor_sync(0xffffffffu, rsum1, 2);
    const float inv0 = 1.0f / rsum0;
    const float inv1 = 1.0f / rsum1;
    const int b = bh >> 3;
    const int row0 = i0 + w * 16 + lr;
    float* o0 = g_o + ((size_t)b * NN + row0) * CC + h * HD;
    float* o1 = o0 + 8 * CC;
#pragma unroll
    for (int nb = 0; nb < 6; ++nb) {
        *(float2*)&o0[nb * 8 + 2 * lc] = make_float2(oacc[nb][0] * inv0, oacc[nb][1] * inv0);
        *(float2*)&o1[nb * 8 + 2 * lc] = make_float2(oacc[nb][2] * inv1, oacc[nb][3] * inv1);
    }
}

// ===========================================================================
// GEMM 2 (tf32 TC): out[b,j,n] = sum_c g_o[b,n,c]*proj_w[j,c]+pb[j]
// R11: 128x128 tile (qkv-shaped), register prefetch, 2-pass smem-transposed
// epilogue (Cs 64x132 reused).
// ===========================================================================
__global__ __launch_bounds__(256) void gemm_proj_tc(const float* __restrict__ w,
                                                    const float* __restrict__ bias,
                                                    float* __restrict__ out) {
    __shared__ float Sm[9216];
    float* As = Sm;               // [m][k] 128x36
    float* Bs = Sm + 128 * 36;    // [j][k] 128x36
    float* Cs = Sm;               // [j][m] 64x132 per pass (8448 <= 9216)

    const int b  = blockIdx.z;
    const int m0 = blockIdx.y * 128;
    const int j0 = blockIdx.x * 128;
    const int t  = threadIdx.x;
    const int w8 = t >> 5, lane = t & 31;
    const int lr = lane >> 2, lc = lane & 3;
    const int wm = w8 & 1, wn = w8 >> 1;   // 2(m) x 4(j)

    float acc[4][4][4];
#pragma unroll
    for (int i = 0; i < 4; ++i)
#pragma unroll
        for (int j = 0; j < 4; ++j)
#pragma unroll
            for (int e = 0; e < 4; ++e) acc[i][j][e] = 0.f;

    const float* A = g_o + (size_t)b * NN * CC;

    float4 apre[4], bpre[4];
#pragma unroll
    for (int r = 0; r < 4; ++r) {
        int idx = t + r * 256;
        int m = idx >> 3, k4 = idx & 7;
        apre[r] = *(const float4*)(A + (size_t)(m0 + m) * CC + k4 * 4);
        bpre[r] = *(const float4*)(w + (size_t)(j0 + m) * CC + k4 * 4);
    }

    for (int k0 = 0; k0 < CC; k0 += 32) {
        __syncthreads();
#pragma unroll
        for (int r = 0; r < 4; ++r) {
            int idx = t + r * 256;
            int m = idx >> 3, k4 = idx & 7;
            float4 v = apre[r];
            v.x = tf32r(v.x); v.y = tf32r(v.y); v.z = tf32r(v.z); v.w = tf32r(v.w);
            *(float4*)&As[m * 36 + k4 * 4] = v;
            float4 u = bpre[r];
            u.x = tf32r(u.x); u.y = tf32r(u.y); u.z = tf32r(u.z); u.w = tf32r(u.w);
            *(float4*)&Bs[m * 36 + k4 * 4] = u;
        }
        if (k0 + 32 < CC) {
            const int k1 = k0 + 32;
#pragma unroll
            for (int r = 0; r < 4; ++r) {
                int idx = t + r * 256;
                int m = idx >> 3, k4 = idx & 7;
                apre[r] = *(const float4*)(A + (size_t)(m0 + m) * CC + k1 + k4 * 4);
                bpre[r] = *(const float4*)(w + (size_t)(j0 + m) * CC + k1 + k4 * 4);
            }
        }
        __syncthreads();
#pragma unroll
        for (int kb = 0; kb < 4; ++kb) {
            float af[4][4], bf[4][2];
#pragma unroll
            for (int mt = 0; mt < 4; ++mt) {
                int base = (wm * 64 + mt * 16 + lr) * 36 + kb * 8 + lc;
                af[mt][0] = As[base];
                af[mt][1] = As[base + 8 * 36];
                af[mt][2] = As[base + 4];
                af[mt][3] = As[base + 8 * 36 + 4];
            }
#pragma unroll
            for (int nb = 0; nb < 4; ++nb) {
                int bb = (wn * 32 + nb * 8 + lr) * 36 + kb * 8 + lc;
                bf[nb][0] = Bs[bb];
                bf[nb][1] = Bs[bb + 4];
            }
#pragma unroll
            for (int mt = 0; mt < 4; ++mt)
#pragma unroll
                for (int nb = 0; nb < 4; ++nb)
                    mma_tf32(acc[mt][nb], af[mt], bf[nb][0], bf[nb][1]);
        }
    }

    // 2-pass epilogue: stage C[j][m] -> coalesced store along n
#pragma unroll
    for (int hh = 0; hh < 2; ++hh) {
        __syncthreads();
        if ((wn >> 1) == hh) {
#pragma unroll
            for (int mt = 0; mt < 4; ++mt) {
                int m1 = wm * 64 + mt * 16 + lr;
                int m2 = m1 + 8;
#pragma unroll
                for (int nb = 0; nb < 4; ++nb) {
                    int jl = (wn & 1) * 32 + nb * 8 + 2 * lc;
                    Cs[jl * 132 + m1]       = acc[mt][nb][0];
                    Cs[(jl + 1) * 132 + m1] = acc[mt][nb][1];
                    Cs[jl * 132 + m2]       = acc[mt][nb][2];
                    Cs[(jl + 1) * 132 + m2] = acc[mt][nb][3];
                }
            }
        }
        __syncthreads();
#pragma unroll
        for (int r = 0; r < 8; ++r) {
            int idx = t + r * 256;
            int jl = idx >> 5, m4 = idx & 31;
            int jg = j0 + hh * 64 + jl;
            float bj = bias[jg];
            float4 v = *(float4*)&Cs[jl * 132 + m4 * 4];
            v.x += bj; v.y += bj; v.z += bj; v.w += bj;
            *(float4*)(out + ((size_t)b * CC + jg) * NN + m0 + m4 * 4) = v;
        }
    }
}

// ===========================================================================
extern "C" void kernel_launch(void* const* d_in, const int* in_sizes, int n_in,
                              void* d_out, int out_size) {
    const float* x      = (const float*)d_in[0];
    const float* temp   = (const float*)d_in[1];
    const float* qkv_w  = (const float*)d_in[2];
    const float* qkv_b  = (const float*)d_in[3];
    const float* proj_w = (const float*)d_in[4];
    const float* proj_b = (const float*)d_in[5];
    float* out = (float*)d_out;

    static const int ATTN_SMEM = ATTN_SMEM_F * 4;   // 66560 bytes
    cudaFuncSetAttribute(attn_mma, cudaFuncAttributeMaxDynamicSharedMemorySize,
                         ATTN_SMEM);

    gemm_qkv_tc<<<dim3(9, 8, BB), 256>>>(x, qkv_w, qkv_b);
    l2norm_kernel<<<32768, 256>>>();
    attn_mma<<<dim3(8, BB * NH), 256, ATTN_SMEM>>>(temp);
    gemm_proj_tc<<<dim3(3, 8, BB), 256>>>(proj_w, proj_b, out);
}